// round 1
// baseline (speedup 1.0000x reference)
#include <cuda_runtime.h>
#include <math.h>
#include <stdint.h>

// Problem constants
#define BATCH 256
#define SEQ   200
#define DIM   300
#define NHEAD 6
#define DHEAD 50
#define NROW  (BATCH*SEQ)        // 51200
#define GELU_C 0.7978845608028654f

// ---------------- scratch (device globals; no cudaMalloc allowed) -------------
__device__ float g_sin[SEQ*DIM];          // sinusoid table
__device__ float g_h  [NROW*DIM];         // current hidden state
__device__ float g_h1 [NROW*DIM];         // post-LN1 hidden
__device__ float g_qkv[NROW*3*DIM];       // QKV activations
__device__ float g_att[NROW*DIM];         // attention output
__device__ float g_prj[NROW*DIM];         // out-projection output
__device__ float g_ff1[NROW*2*DIM];       // FF hidden (600)
__device__ float g_ff2[NROW*DIM];         // FF output
__device__ float g_s1 [NROW];             // head: lin1 output [B,S]
__device__ unsigned char g_mask[NROW];    // padding mask (True = pad)

__device__ __forceinline__ float gelu_f(float x) {
    float x3 = x*x*x;
    return 0.5f*x*(1.0f + tanhf(GELU_C*(x + 0.044715f*x3)));
}

// ---------------- sinusoid table (double precision to match numpy) ------------
__global__ void sin_table_kernel() {
    int idx = blockIdx.x*blockDim.x + threadIdx.x;
    if (idx >= SEQ*DIM) return;
    int pos = idx / DIM, i = idx % DIM;
    double ang = (double)pos / pow(10000.0, 2.0*(double)(i/2)/(double)DIM);
    g_sin[idx] = (float)((i & 1) ? cos(ang) : sin(ang));
}

// ---------------- embedding + positional encoding + initial mask --------------
__global__ void embed_kernel(const int* __restrict__ tok,
                             const float* __restrict__ emb) {
    int idx = blockIdx.x*blockDim.x + threadIdx.x;
    if (idx >= NROW*DIM) return;
    int r = idx / DIM, d = idx % DIM;
    int t = tok[r];
    float v = emb[(size_t)t*DIM + d];
    if (t != 0) v += g_sin[(r % SEQ)*DIM + d];
    g_h[idx] = v;
    if (d == 0) g_mask[r] = (t == 0) ? 1 : 0;
}

// ---------------- generic SGEMM: C[M,N] = A[M,K] @ B[K,N] + bias (+gelu) ------
// BM=BN=64, BK=16, 256 threads, 4x4 per thread.
__global__ void sgemm_kernel(const float* __restrict__ A,
                             const float* __restrict__ B,
                             const float* __restrict__ bias,
                             float* __restrict__ C,
                             int M, int N, int K, int act) {
    const int BM=64, BN=64, BK=16;
    __shared__ float As[BK][BM+4];
    __shared__ float Bs[BK][BN];
    int tid = threadIdx.x;
    int bm = blockIdx.y*BM, bn = blockIdx.x*BN;
    int tx = tid & 15, ty = tid >> 4;
    float acc[4][4] = {};

    for (int k0 = 0; k0 < K; k0 += BK) {
        #pragma unroll
        for (int i = 0; i < 4; i++) {           // A tile: 64x16
            int idx = tid + i*256;
            int m = idx >> 4, kk = idx & 15;
            int gk = k0 + kk;
            As[kk][m] = (gk < K) ? A[(size_t)(bm+m)*K + gk] : 0.0f;
        }
        #pragma unroll
        for (int i = 0; i < 4; i++) {           // B tile: 16x64
            int idx = tid + i*256;
            int kk = idx >> 6, n = idx & 63;
            int gk = k0 + kk, gn = bn + n;
            Bs[kk][n] = (gk < K && gn < N) ? B[(size_t)gk*N + gn] : 0.0f;
        }
        __syncthreads();
        #pragma unroll
        for (int kk = 0; kk < BK; kk++) {
            float4 a4 = *(const float4*)&As[kk][ty*4];
            float4 b4 = *(const float4*)&Bs[kk][tx*4];
            float a[4] = {a4.x, a4.y, a4.z, a4.w};
            float b[4] = {b4.x, b4.y, b4.z, b4.w};
            #pragma unroll
            for (int i = 0; i < 4; i++)
                #pragma unroll
                for (int j = 0; j < 4; j++)
                    acc[i][j] += a[i]*b[j];
        }
        __syncthreads();
    }
    #pragma unroll
    for (int i = 0; i < 4; i++) {
        int gm = bm + ty*4 + i;
        #pragma unroll
        for (int j = 0; j < 4; j++) {
            int gn = bn + tx*4 + j;
            if (gn < N) {
                float v = acc[i][j] + bias[gn];
                if (act == 1) v = gelu_f(v);
                C[(size_t)gm*N + gn] = v;
            }
        }
    }
}

// ---------------- fused attention per (b,h) -----------------------------------
// K tile + per-warp scores in static smem; V read through L1.
__global__ void attn_kernel(const float* __restrict__ qkv,
                            const unsigned char* __restrict__ mask,
                            float* __restrict__ out) {
    __shared__ float Ks[SEQ][DHEAD];     // 40000 B
    __shared__ float sc[8][SEQ];         // 6400 B
    __shared__ unsigned char mk[SEQ];

    int b = blockIdx.x / NHEAD, h = blockIdx.x % NHEAD;
    int tid = threadIdx.x, w = tid >> 5, lane = tid & 31;

    if (tid < SEQ) mk[tid] = mask[b*SEQ + tid];
    int padcnt = __syncthreads_count(tid < SEQ && mask[b*SEQ + tid]);
    bool allpad = (padcnt == SEQ);

    for (int idx = tid; idx < SEQ*DHEAD; idx += blockDim.x) {
        int s = idx / DHEAD, d = idx % DHEAD;
        Ks[s][d] = qkv[(size_t)(b*SEQ + s)*900 + 300 + h*DHEAD + d];
    }
    __syncthreads();

    const float scale = 0.1414213562373095f;  // 1/sqrt(50)

    for (int q = w; q < SEQ; q += 8) {
        const float* qp = &qkv[(size_t)(b*SEQ + q)*900 + h*DHEAD];
        float qreg[DHEAD];
        #pragma unroll
        for (int d = 0; d < DHEAD; d++) qreg[d] = qp[d];

        float smax = -INFINITY;
        for (int k = lane; k < SEQ; k += 32) {
            float s;
            if (!mk[k]) {
                s = 0.0f;
                #pragma unroll
                for (int d = 0; d < DHEAD; d++) s += qreg[d]*Ks[k][d];
                s *= scale;
                smax = fmaxf(smax, s);
            } else {
                s = -INFINITY;
            }
            sc[w][k] = s;
        }
        #pragma unroll
        for (int off = 16; off > 0; off >>= 1)
            smax = fmaxf(smax, __shfl_xor_sync(0xffffffffu, smax, off));

        float psum = 0.0f;
        __syncwarp();
        for (int k = lane; k < SEQ; k += 32) {
            float e = mk[k] ? 0.0f : expf(sc[w][k] - smax);
            sc[w][k] = e;
            psum += e;
        }
        #pragma unroll
        for (int off = 16; off > 0; off >>= 1)
            psum += __shfl_xor_sync(0xffffffffu, psum, off);
        float inv = (allpad || psum == 0.0f) ? 0.0f : 1.0f/psum;
        __syncwarp();

        for (int d = lane; d < DHEAD; d += 32) {
            float acc = 0.0f;
            for (int k = 0; k < SEQ; k++)
                acc += sc[w][k] * qkv[(size_t)(b*SEQ + k)*900 + 600 + h*DHEAD + d];
            out[(size_t)(b*SEQ + q)*DIM + h*DHEAD + d] = acc*inv;
        }
        __syncwarp();
    }
}

// ---------------- fused residual add + LayerNorm (+ optional mask recompute) --
__global__ void ln_kernel(const float* __restrict__ X,
                          const float* __restrict__ Y,
                          const float* __restrict__ s,
                          const float* __restrict__ bcoef,
                          float* __restrict__ out,
                          unsigned char* maskout) {
    __shared__ float red[4];
    int r = blockIdx.x, tid = threadIdx.x;   // 128 threads
    float v[3]; int nd = 0;
    float local = 0.0f;
    for (int d = tid; d < DIM; d += 128) {
        float t = X[(size_t)r*DIM + d] + Y[(size_t)r*DIM + d];
        v[nd++] = t;
        local += t;
    }
    // block reduce sum
    #pragma unroll
    for (int off = 16; off > 0; off >>= 1) local += __shfl_xor_sync(0xffffffffu, local, off);
    if ((tid & 31) == 0) red[tid >> 5] = local;
    __syncthreads();
    float mean = (red[0] + red[1] + red[2] + red[3]) / (float)DIM;
    __syncthreads();

    local = 0.0f;
    for (int i = 0; i < nd; i++) { float d0 = v[i] - mean; local += d0*d0; }
    #pragma unroll
    for (int off = 16; off > 0; off >>= 1) local += __shfl_xor_sync(0xffffffffu, local, off);
    if ((tid & 31) == 0) red[tid >> 5] = local;
    __syncthreads();
    float var = (red[0] + red[1] + red[2] + red[3]) / (float)DIM;
    float rstd = 1.0f / sqrtf(var + 1e-5f);

    bool allz = true;
    int nd2 = 0;
    for (int d = tid; d < DIM; d += 128) {
        float o = (v[nd2++] - mean)*rstd*s[d] + bcoef[d];
        out[(size_t)r*DIM + d] = o;
        if (o != 0.0f) allz = false;
    }
    if (maskout) {
        int cnt = __syncthreads_count(allz ? 1 : 0);
        if (tid == 0) maskout[r] = (cnt == 128) ? 1 : 0;
    }
}

// ---------------- head: s1 = h @ lin1_w + b (warp per row) --------------------
__global__ void rowdot_kernel(const float* __restrict__ w1,
                              const float* __restrict__ b1) {
    int tid = threadIdx.x, warp = tid >> 5, lane = tid & 31;
    int r = blockIdx.x*8 + warp;
    if (r >= NROW) return;
    float acc = 0.0f;
    for (int d = lane; d < DIM; d += 32)
        acc += g_h[(size_t)r*DIM + d] * w1[d];
    #pragma unroll
    for (int off = 16; off > 0; off >>= 1) acc += __shfl_xor_sync(0xffffffffu, acc, off);
    if (lane == 0) g_s1[r] = acc + b1[0];
}

// ---------------- head: gelu(s1 @ lin2 + b) -> out / aux ----------------------
__global__ void head_kernel(const float* __restrict__ w2, const float* __restrict__ b2,
                            const float* __restrict__ wo, const float* __restrict__ bo,
                            const float* __restrict__ wa, const float* __restrict__ ba,
                            float* __restrict__ out) {
    __shared__ float s1s[SEQ];
    __shared__ float s2s[50];
    int b = blockIdx.x, tid = threadIdx.x;     // 64 threads
    for (int i = tid; i < SEQ; i += 64) s1s[i] = g_s1[b*SEQ + i];
    __syncthreads();
    if (tid < 50) {
        float acc = 0.0f;
        for (int s = 0; s < SEQ; s++) acc += s1s[s]*w2[s*50 + tid];
        s2s[tid] = gelu_f(acc + b2[tid]);
    }
    __syncthreads();
    if (tid < 7) {
        float acc = 0.0f;
        if (tid == 0) {
            for (int i = 0; i < 50; i++) acc += s2s[i]*wo[i];
            out[b*7] = acc + bo[0];
        } else {
            int j = tid - 1;
            for (int i = 0; i < 50; i++) acc += s2s[i]*wa[i*6 + j];
            out[b*7 + tid] = acc + ba[j];
        }
    }
}

// ---------------- launch ------------------------------------------------------
extern "C" void kernel_launch(void* const* d_in, const int* in_sizes, int n_in,
                              void* d_out, int out_size) {
    const int*   x_tok  = (const int*)  d_in[0];
    const float* emb    = (const float*)d_in[1];
    const float* qkv_w  = (const float*)d_in[2];
    const float* qkv_b  = (const float*)d_in[3];
    const float* out_w  = (const float*)d_in[4];
    const float* out_b  = (const float*)d_in[5];
    const float* ln1_s  = (const float*)d_in[6];
    const float* ln1_b  = (const float*)d_in[7];
    const float* ff1_w  = (const float*)d_in[8];
    const float* ff1_b  = (const float*)d_in[9];
    const float* ff2_w  = (const float*)d_in[10];
    const float* ff2_b  = (const float*)d_in[11];
    const float* ln2_s  = (const float*)d_in[12];
    const float* ln2_b  = (const float*)d_in[13];
    const float* lin1_w = (const float*)d_in[14];
    const float* lin1_b = (const float*)d_in[15];
    const float* lin2_w = (const float*)d_in[16];
    const float* lin2_b = (const float*)d_in[17];
    const float* lout_w = (const float*)d_in[18];
    const float* lout_b = (const float*)d_in[19];
    const float* laux_w = (const float*)d_in[20];
    const float* laux_b = (const float*)d_in[21];

    float *p_h, *p_h1, *p_qkv, *p_att, *p_prj, *p_ff1, *p_ff2;
    unsigned char *p_mask;
    cudaGetSymbolAddress((void**)&p_h,   g_h);
    cudaGetSymbolAddress((void**)&p_h1,  g_h1);
    cudaGetSymbolAddress((void**)&p_qkv, g_qkv);
    cudaGetSymbolAddress((void**)&p_att, g_att);
    cudaGetSymbolAddress((void**)&p_prj, g_prj);
    cudaGetSymbolAddress((void**)&p_ff1, g_ff1);
    cudaGetSymbolAddress((void**)&p_ff2, g_ff2);
    cudaGetSymbolAddress((void**)&p_mask, g_mask);

    sin_table_kernel<<<(SEQ*DIM + 255)/256, 256>>>();
    embed_kernel<<<(NROW*DIM + 255)/256, 256>>>(x_tok, emb);

    for (int l = 0; l < 5; l++) {
        // QKV: [51200,300] @ [300,900]
        sgemm_kernel<<<dim3(15, NROW/64), 256>>>(p_h, qkv_w + (size_t)l*DIM*3*DIM,
                                                 qkv_b + l*3*DIM, p_qkv,
                                                 NROW, 3*DIM, DIM, 0);
        attn_kernel<<<BATCH*NHEAD, 256>>>(p_qkv, p_mask, p_att);
        // out proj: [51200,300] @ [300,300]
        sgemm_kernel<<<dim3(5, NROW/64), 256>>>(p_att, out_w + (size_t)l*DIM*DIM,
                                                out_b + l*DIM, p_prj,
                                                NROW, DIM, DIM, 0);
        ln_kernel<<<NROW, 128>>>(p_h, p_prj, ln1_s + l*DIM, ln1_b + l*DIM, p_h1, nullptr);
        // FF1 + gelu: [51200,300] @ [300,600]
        sgemm_kernel<<<dim3(10, NROW/64), 256>>>(p_h1, ff1_w + (size_t)l*DIM*2*DIM,
                                                 ff1_b + l*2*DIM, p_ff1,
                                                 NROW, 2*DIM, DIM, 1);
        // FF2: [51200,600] @ [600,300]
        sgemm_kernel<<<dim3(5, NROW/64), 256>>>(p_ff1, ff2_w + (size_t)l*2*DIM*DIM,
                                                ff2_b + l*DIM, p_ff2,
                                                NROW, DIM, 2*DIM, 0);
        ln_kernel<<<NROW, 128>>>(p_h1, p_ff2, ln2_s + l*DIM, ln2_b + l*DIM, p_h, p_mask);
    }

    rowdot_kernel<<<NROW/8, 256>>>(lin1_w, lin1_b);
    head_kernel<<<BATCH, 64>>>(lin2_w, lin2_b, lout_w, lout_b, laux_w, laux_b,
                               (float*)d_out);
}

// round 2
// speedup vs baseline: 1.5608x; 1.5608x over previous
#include <cuda_runtime.h>
#include <math.h>
#include <stdint.h>

// Problem constants
#define BATCH 256
#define SEQ   200
#define DIM   300
#define NHEAD 6
#define DHEAD 50
#define NROW  (BATCH*SEQ)        // 51200
#define GELU_C 0.7978845608028654f

// ---------------- scratch (device globals; no cudaMalloc allowed) -------------
__device__ float g_sin[SEQ*DIM];          // sinusoid table
__device__ float g_h  [NROW*DIM];         // current hidden state
__device__ float g_h1 [NROW*DIM];         // post-LN1 hidden
__device__ float g_qkv[NROW*3*DIM];       // QKV activations
__device__ float g_att[NROW*DIM];         // attention output
__device__ float g_prj[NROW*DIM];         // out-projection / ff2 output
__device__ float g_ff1[NROW*2*DIM];       // FF hidden (600)
__device__ float g_ff2[NROW*DIM];
__device__ float g_s1 [NROW];             // head: lin1 output [B,S]
__device__ unsigned char g_mask[NROW];    // padding mask (True = pad)

// packed tf32 weights (zero padded to Kp x Np)
__device__ float g_pw_qkv[320*960];
__device__ float g_pw_prj[320*320];
__device__ float g_pw_ff1[320*640];
__device__ float g_pw_ff2[608*320];

__device__ __forceinline__ float gelu_f(float x) {
    float x3 = x*x*x;
    return 0.5f*x*(1.0f + tanhf(GELU_C*(x + 0.044715f*x3)));
}

__device__ __forceinline__ float to_tf32(float v) {
    uint32_t t;
    asm("cvt.rna.tf32.f32 %0, %1;" : "=r"(t) : "f"(v));
    return __uint_as_float(t);
}

// ---------------- sinusoid table (double precision to match numpy) ------------
__global__ void sin_table_kernel() {
    int idx = blockIdx.x*blockDim.x + threadIdx.x;
    if (idx >= SEQ*DIM) return;
    int pos = idx / DIM, i = idx % DIM;
    double ang = (double)pos / pow(10000.0, 2.0*(double)(i/2)/(double)DIM);
    g_sin[idx] = (float)((i & 1) ? cos(ang) : sin(ang));
}

// ---------------- embedding + positional encoding + initial mask --------------
__global__ void embed_kernel(const int* __restrict__ tok,
                             const float* __restrict__ emb) {
    int idx = blockIdx.x*blockDim.x + threadIdx.x;
    if (idx >= NROW*DIM) return;
    int r = idx / DIM, d = idx % DIM;
    int t = tok[r];
    float v = emb[(size_t)t*DIM + d];
    if (t != 0) v += g_sin[(r % SEQ)*DIM + d];
    g_h[idx] = v;
    if (d == 0) g_mask[r] = (t == 0) ? 1 : 0;
}

// ---------------- weight packing: [K,N] -> padded tf32 [Kp,Np] ----------------
__global__ void pack_w_kernel(const float* __restrict__ src, float* __restrict__ dst,
                              int K, int N, int Kp, int Np) {
    int i = blockIdx.x*blockDim.x + threadIdx.x;
    if (i >= Kp*Np) return;
    int k = i / Np, n = i % Np;
    float v = (k < K && n < N) ? src[(size_t)k*N + n] : 0.0f;
    dst[i] = to_tf32(v);
}

// ---------------- TF32 tensor-core GEMM ---------------------------------------
// C[M,N] = A[M,K] @ Bp[Kp,Np] + bias, optional gelu. M % 128 == 0.
// Block: 128 threads (4 warps, 2x2), tile BM=128 BN=64 BK=32; warp = 64m x 32n.
#define BM 128
#define BN 64
#define BK 32

__global__ __launch_bounds__(128) void mma_gemm_kernel(
        const float* __restrict__ A, const float* __restrict__ Bp,
        const float* __restrict__ bias, float* __restrict__ C,
        int M, int N, int K, int Kp, int Np, int act) {
    __shared__ float As[BM][BK+4];   // stride 36: bank = (4m+k)%32, conflict-free frags
    __shared__ float Bs[BK][BN+8];   // stride 72: bank = (8k+n)%32, conflict-free frags

    int tid = threadIdx.x;
    int warp = tid >> 5, lane = tid & 31;
    int g = lane >> 2, tig = lane & 3;
    int warpM = warp >> 1, warpN = warp & 1;
    int mw = warpM*64, nw = warpN*32;
    int bm = blockIdx.y*BM, bn = blockIdx.x*BN;

    float acc[4][4][4];
    #pragma unroll
    for (int i = 0; i < 4; i++)
        #pragma unroll
        for (int j = 0; j < 4; j++)
            #pragma unroll
            for (int r = 0; r < 4; r++) acc[i][j][r] = 0.0f;

    for (int k0 = 0; k0 < Kp; k0 += BK) {
        // load A tile: 128 rows x 8 float4 (K%4==0 so whole-float4 guard works)
        #pragma unroll
        for (int it = 0; it < 8; it++) {
            int i = tid + it*128;
            int m = i >> 3, kt = (i & 7)*4;
            int gk = k0 + kt;
            float4 v = make_float4(0.f,0.f,0.f,0.f);
            if (gk < K) v = *(const float4*)&A[(size_t)(bm+m)*K + gk];
            As[m][kt+0] = to_tf32(v.x);
            As[m][kt+1] = to_tf32(v.y);
            As[m][kt+2] = to_tf32(v.z);
            As[m][kt+3] = to_tf32(v.w);
        }
        // load B tile: 32 rows x 16 float4 (pre-padded, no guard)
        #pragma unroll
        for (int it = 0; it < 4; it++) {
            int i = tid + it*128;
            int k = i >> 4, nt = (i & 15)*4;
            float4 v = *(const float4*)&Bp[(size_t)(k0+k)*Np + bn + nt];
            Bs[k][nt+0] = v.x;
            Bs[k][nt+1] = v.y;
            Bs[k][nt+2] = v.z;
            Bs[k][nt+3] = v.w;
        }
        __syncthreads();

        #pragma unroll
        for (int ks = 0; ks < 4; ks++) {
            int kb = ks*8;
            uint32_t af[4][4], bf[4][2];
            #pragma unroll
            for (int mt = 0; mt < 4; mt++) {
                int rm = mw + mt*16;
                af[mt][0] = __float_as_uint(As[rm + g    ][kb + tig    ]);
                af[mt][1] = __float_as_uint(As[rm + g + 8][kb + tig    ]);
                af[mt][2] = __float_as_uint(As[rm + g    ][kb + tig + 4]);
                af[mt][3] = __float_as_uint(As[rm + g + 8][kb + tig + 4]);
            }
            #pragma unroll
            for (int nt = 0; nt < 4; nt++) {
                int cn = nw + nt*8;
                bf[nt][0] = __float_as_uint(Bs[kb + tig    ][cn + g]);
                bf[nt][1] = __float_as_uint(Bs[kb + tig + 4][cn + g]);
            }
            #pragma unroll
            for (int mt = 0; mt < 4; mt++)
                #pragma unroll
                for (int nt = 0; nt < 4; nt++) {
                    asm volatile(
                        "mma.sync.aligned.m16n8k8.row.col.f32.tf32.tf32.f32 "
                        "{%0,%1,%2,%3}, {%4,%5,%6,%7}, {%8,%9}, {%0,%1,%2,%3};"
                        : "+f"(acc[mt][nt][0]), "+f"(acc[mt][nt][1]),
                          "+f"(acc[mt][nt][2]), "+f"(acc[mt][nt][3])
                        : "r"(af[mt][0]), "r"(af[mt][1]), "r"(af[mt][2]), "r"(af[mt][3]),
                          "r"(bf[nt][0]), "r"(bf[nt][1]));
                }
        }
        __syncthreads();
    }

    // epilogue: bias (+gelu), guard n < N (N even, cols even -> single guard)
    #pragma unroll
    for (int mt = 0; mt < 4; mt++) {
        int row0 = bm + mw + mt*16 + g;
        #pragma unroll
        for (int nt = 0; nt < 4; nt++) {
            int col = bn + nw + nt*8 + tig*2;
            if (col < N) {
                float b0 = bias[col], b1 = bias[col+1];
                float v0 = acc[mt][nt][0] + b0;
                float v1 = acc[mt][nt][1] + b1;
                float v2 = acc[mt][nt][2] + b0;
                float v3 = acc[mt][nt][3] + b1;
                if (act == 1) { v0 = gelu_f(v0); v1 = gelu_f(v1); v2 = gelu_f(v2); v3 = gelu_f(v3); }
                *(float2*)&C[(size_t)row0*N + col]     = make_float2(v0, v1);
                *(float2*)&C[(size_t)(row0+8)*N + col] = make_float2(v2, v3);
            }
        }
    }
}

// ---------------- fused attention per (b,h) -----------------------------------
__global__ void attn_kernel(const float* __restrict__ qkv,
                            const unsigned char* __restrict__ mask,
                            float* __restrict__ out) {
    __shared__ float Ks[SEQ][DHEAD];     // 40000 B
    __shared__ float sc[8][SEQ];         // 6400 B
    __shared__ unsigned char mk[SEQ];

    int b = blockIdx.x / NHEAD, h = blockIdx.x % NHEAD;
    int tid = threadIdx.x, w = tid >> 5, lane = tid & 31;

    if (tid < SEQ) mk[tid] = mask[b*SEQ + tid];
    int padcnt = __syncthreads_count(tid < SEQ && mask[b*SEQ + tid]);
    bool allpad = (padcnt == SEQ);

    for (int idx = tid; idx < SEQ*DHEAD; idx += blockDim.x) {
        int s = idx / DHEAD, d = idx % DHEAD;
        Ks[s][d] = qkv[(size_t)(b*SEQ + s)*900 + 300 + h*DHEAD + d];
    }
    __syncthreads();

    const float scale = 0.1414213562373095f;  // 1/sqrt(50)

    for (int q = w; q < SEQ; q += 8) {
        const float* qp = &qkv[(size_t)(b*SEQ + q)*900 + h*DHEAD];
        float qreg[DHEAD];
        #pragma unroll
        for (int d = 0; d < DHEAD; d++) qreg[d] = qp[d];

        float smax = -INFINITY;
        for (int k = lane; k < SEQ; k += 32) {
            float s;
            if (!mk[k]) {
                s = 0.0f;
                #pragma unroll
                for (int d = 0; d < DHEAD; d++) s += qreg[d]*Ks[k][d];
                s *= scale;
                smax = fmaxf(smax, s);
            } else {
                s = -INFINITY;
            }
            sc[w][k] = s;
        }
        #pragma unroll
        for (int off = 16; off > 0; off >>= 1)
            smax = fmaxf(smax, __shfl_xor_sync(0xffffffffu, smax, off));

        float psum = 0.0f;
        __syncwarp();
        for (int k = lane; k < SEQ; k += 32) {
            float e = mk[k] ? 0.0f : expf(sc[w][k] - smax);
            sc[w][k] = e;
            psum += e;
        }
        #pragma unroll
        for (int off = 16; off > 0; off >>= 1)
            psum += __shfl_xor_sync(0xffffffffu, psum, off);
        float inv = (allpad || psum == 0.0f) ? 0.0f : 1.0f/psum;
        __syncwarp();

        for (int d = lane; d < DHEAD; d += 32) {
            float acc2 = 0.0f;
            for (int k = 0; k < SEQ; k++)
                acc2 += sc[w][k] * qkv[(size_t)(b*SEQ + k)*900 + 600 + h*DHEAD + d];
            out[(size_t)(b*SEQ + q)*DIM + h*DHEAD + d] = acc2*inv;
        }
        __syncwarp();
    }
}

// ---------------- fused residual add + LayerNorm (+ optional mask recompute) --
__global__ void ln_kernel(const float* __restrict__ X,
                          const float* __restrict__ Y,
                          const float* __restrict__ s,
                          const float* __restrict__ bcoef,
                          float* __restrict__ out,
                          unsigned char* maskout) {
    __shared__ float red[4];
    int r = blockIdx.x, tid = threadIdx.x;   // 128 threads
    float v[3]; int nd = 0;
    float local = 0.0f;
    for (int d = tid; d < DIM; d += 128) {
        float t = X[(size_t)r*DIM + d] + Y[(size_t)r*DIM + d];
        v[nd++] = t;
        local += t;
    }
    #pragma unroll
    for (int off = 16; off > 0; off >>= 1) local += __shfl_xor_sync(0xffffffffu, local, off);
    if ((tid & 31) == 0) red[tid >> 5] = local;
    __syncthreads();
    float mean = (red[0] + red[1] + red[2] + red[3]) / (float)DIM;
    __syncthreads();

    local = 0.0f;
    for (int i = 0; i < nd; i++) { float d0 = v[i] - mean; local += d0*d0; }
    #pragma unroll
    for (int off = 16; off > 0; off >>= 1) local += __shfl_xor_sync(0xffffffffu, local, off);
    if ((tid & 31) == 0) red[tid >> 5] = local;
    __syncthreads();
    float var = (red[0] + red[1] + red[2] + red[3]) / (float)DIM;
    float rstd = 1.0f / sqrtf(var + 1e-5f);

    bool allz = true;
    int nd2 = 0;
    for (int d = tid; d < DIM; d += 128) {
        float o = (v[nd2++] - mean)*rstd*s[d] + bcoef[d];
        out[(size_t)r*DIM + d] = o;
        if (o != 0.0f) allz = false;
    }
    if (maskout) {
        int cnt = __syncthreads_count(allz ? 1 : 0);
        if (tid == 0) maskout[r] = (cnt == 128) ? 1 : 0;
    }
}

// ---------------- head: s1 = h @ lin1_w + b (warp per row) --------------------
__global__ void rowdot_kernel(const float* __restrict__ w1,
                              const float* __restrict__ b1) {
    int tid = threadIdx.x, warp = tid >> 5, lane = tid & 31;
    int r = blockIdx.x*8 + warp;
    if (r >= NROW) return;
    float acc = 0.0f;
    for (int d = lane; d < DIM; d += 32)
        acc += g_h[(size_t)r*DIM + d] * w1[d];
    #pragma unroll
    for (int off = 16; off > 0; off >>= 1) acc += __shfl_xor_sync(0xffffffffu, acc, off);
    if (lane == 0) g_s1[r] = acc + b1[0];
}

// ---------------- head: gelu(s1 @ lin2 + b) -> out / aux ----------------------
__global__ void head_kernel(const float* __restrict__ w2, const float* __restrict__ b2,
                            const float* __restrict__ wo, const float* __restrict__ bo,
                            const float* __restrict__ wa, const float* __restrict__ ba,
                            float* __restrict__ out) {
    __shared__ float s1s[SEQ];
    __shared__ float s2s[50];
    int b = blockIdx.x, tid = threadIdx.x;     // 64 threads
    for (int i = tid; i < SEQ; i += 64) s1s[i] = g_s1[b*SEQ + i];
    __syncthreads();
    if (tid < 50) {
        float acc = 0.0f;
        for (int s = 0; s < SEQ; s++) acc += s1s[s]*w2[s*50 + tid];
        s2s[tid] = gelu_f(acc + b2[tid]);
    }
    __syncthreads();
    if (tid < 7) {
        float acc = 0.0f;
        if (tid == 0) {
            for (int i = 0; i < 50; i++) acc += s2s[i]*wo[i];
            out[b*7] = acc + bo[0];
        } else {
            int j = tid - 1;
            for (int i = 0; i < 50; i++) acc += s2s[i]*wa[i*6 + j];
            out[b*7 + tid] = acc + ba[j];
        }
    }
}

// ---------------- launch ------------------------------------------------------
extern "C" void kernel_launch(void* const* d_in, const int* in_sizes, int n_in,
                              void* d_out, int out_size) {
    const int*   x_tok  = (const int*)  d_in[0];
    const float* emb    = (const float*)d_in[1];
    const float* qkv_w  = (const float*)d_in[2];
    const float* qkv_b  = (const float*)d_in[3];
    const float* out_w  = (const float*)d_in[4];
    const float* out_b  = (const float*)d_in[5];
    const float* ln1_s  = (const float*)d_in[6];
    const float* ln1_b  = (const float*)d_in[7];
    const float* ff1_w  = (const float*)d_in[8];
    const float* ff1_b  = (const float*)d_in[9];
    const float* ff2_w  = (const float*)d_in[10];
    const float* ff2_b  = (const float*)d_in[11];
    const float* ln2_s  = (const float*)d_in[12];
    const float* ln2_b  = (const float*)d_in[13];
    const float* lin1_w = (const float*)d_in[14];
    const float* lin1_b = (const float*)d_in[15];
    const float* lin2_w = (const float*)d_in[16];
    const float* lin2_b = (const float*)d_in[17];
    const float* lout_w = (const float*)d_in[18];
    const float* lout_b = (const float*)d_in[19];
    const float* laux_w = (const float*)d_in[20];
    const float* laux_b = (const float*)d_in[21];

    float *p_h, *p_h1, *p_qkv, *p_att, *p_prj, *p_ff1, *p_ff2;
    float *p_wqkv, *p_wprj, *p_wff1, *p_wff2;
    unsigned char *p_mask;
    cudaGetSymbolAddress((void**)&p_h,   g_h);
    cudaGetSymbolAddress((void**)&p_h1,  g_h1);
    cudaGetSymbolAddress((void**)&p_qkv, g_qkv);
    cudaGetSymbolAddress((void**)&p_att, g_att);
    cudaGetSymbolAddress((void**)&p_prj, g_prj);
    cudaGetSymbolAddress((void**)&p_ff1, g_ff1);
    cudaGetSymbolAddress((void**)&p_ff2, g_ff2);
    cudaGetSymbolAddress((void**)&p_mask, g_mask);
    cudaGetSymbolAddress((void**)&p_wqkv, g_pw_qkv);
    cudaGetSymbolAddress((void**)&p_wprj, g_pw_prj);
    cudaGetSymbolAddress((void**)&p_wff1, g_pw_ff1);
    cudaGetSymbolAddress((void**)&p_wff2, g_pw_ff2);

    sin_table_kernel<<<(SEQ*DIM + 255)/256, 256>>>();
    embed_kernel<<<(NROW*DIM + 255)/256, 256>>>(x_tok, emb);

    for (int l = 0; l < 5; l++) {
        // pack weights (tf32, zero-padded)
        pack_w_kernel<<<(320*960+255)/256, 256>>>(qkv_w + (size_t)l*DIM*3*DIM, p_wqkv,
                                                  300, 900, 320, 960);
        pack_w_kernel<<<(320*320+255)/256, 256>>>(out_w + (size_t)l*DIM*DIM, p_wprj,
                                                  300, 300, 320, 320);
        pack_w_kernel<<<(320*640+255)/256, 256>>>(ff1_w + (size_t)l*DIM*2*DIM, p_wff1,
                                                  300, 600, 320, 640);
        pack_w_kernel<<<(608*320+255)/256, 256>>>(ff2_w + (size_t)l*2*DIM*DIM, p_wff2,
                                                  600, 300, 608, 320);

        // QKV: [51200,300] @ [300,900]
        mma_gemm_kernel<<<dim3(960/BN, NROW/BM), 128>>>(p_h, p_wqkv,
            qkv_b + l*3*DIM, p_qkv, NROW, 900, 300, 320, 960, 0);
        attn_kernel<<<BATCH*NHEAD, 256>>>(p_qkv, p_mask, p_att);
        // out proj: [51200,300] @ [300,300]
        mma_gemm_kernel<<<dim3(320/BN, NROW/BM), 128>>>(p_att, p_wprj,
            out_b + l*DIM, p_prj, NROW, 300, 300, 320, 320, 0);
        ln_kernel<<<NROW, 128>>>(p_h, p_prj, ln1_s + l*DIM, ln1_b + l*DIM, p_h1, nullptr);
        // FF1 + gelu: [51200,300] @ [300,600]
        mma_gemm_kernel<<<dim3(640/BN, NROW/BM), 128>>>(p_h1, p_wff1,
            ff1_b + l*2*DIM, p_ff1, NROW, 600, 300, 320, 640, 1);
        // FF2: [51200,600] @ [600,300]
        mma_gemm_kernel<<<dim3(320/BN, NROW/BM), 128>>>(p_ff1, p_wff2,
            ff2_b + l*DIM, p_ff2, NROW, 300, 600, 608, 320, 0);
        ln_kernel<<<NROW, 128>>>(p_h1, p_ff2, ln2_s + l*DIM, ln2_b + l*DIM, p_h, p_mask);
    }

    rowdot_kernel<<<NROW/8, 256>>>(lin1_w, lin1_b);
    head_kernel<<<BATCH, 64>>>(lin2_w, lin2_b, lout_w, lout_b, laux_w, laux_b,
                               (float*)d_out);
}

// round 4
// speedup vs baseline: 2.2112x; 1.4167x over previous
#include <cuda_runtime.h>
#include <math.h>
#include <stdint.h>

// Problem constants
#define BATCH 256
#define SEQ   200
#define DIM   300
#define NHEAD 6
#define DHEAD 50
#define NROW  (BATCH*SEQ)        // 51200
#define LDH   320                // padded stride for D=300 activations
#define LDF   608                // padded stride for 600-dim FF hidden
#define GELU_C 0.7978845608028654f

// ---------------- scratch (device globals; zero-initialized) ------------------
__device__ float g_sin[SEQ*DIM];
__device__ float g_h  [NROW*LDH];
__device__ float g_h1 [NROW*LDH];
__device__ float g_qkv[NROW*900];
__device__ float g_att[NROW*LDH];
__device__ float g_prj[NROW*LDH];
__device__ float g_ff1[NROW*LDF];
__device__ float g_ff2[NROW*LDH];
__device__ float g_s1 [NROW];
__device__ unsigned char g_mask[NROW];

// packed tf32 weights, all 5 layers, zero padded to Kp x Np
__device__ float g_pw_qkv[5*320*1024];
__device__ float g_pw_prj[5*320*384];
__device__ float g_pw_ff1[5*320*640];
__device__ float g_pw_ff2[5*608*384];

__device__ __forceinline__ float gelu_f(float x) {
    float x3 = x*x*x;
    return 0.5f*x*(1.0f + tanhf(GELU_C*(x + 0.044715f*x3)));
}
__device__ __forceinline__ float to_tf32(float v) {
    uint32_t t;
    asm("cvt.rna.tf32.f32 %0, %1;" : "=r"(t) : "f"(v));
    return __uint_as_float(t);
}
__device__ __forceinline__ uint32_t smemu32(const void* p) {
    return (uint32_t)__cvta_generic_to_shared(p);
}
#define CP16(dst, src) asm volatile("cp.async.cg.shared.global [%0], [%1], 16;\n" :: "r"(dst), "l"(src))
#define CP_COMMIT()    asm volatile("cp.async.commit_group;\n" ::)
#define CP_WAIT(N)     asm volatile("cp.async.wait_group %0;\n" :: "n"(N))

// ---------------- sinusoid table ----------------------------------------------
__global__ void sin_table_kernel() {
    int idx = blockIdx.x*blockDim.x + threadIdx.x;
    if (idx >= SEQ*DIM) return;
    int pos = idx / DIM, i = idx % DIM;
    double ang = (double)pos / pow(10000.0, 2.0*(double)(i/2)/(double)DIM);
    g_sin[idx] = (float)((i & 1) ? cos(ang) : sin(ang));
}

// ---------------- embedding + pos-enc + initial mask --------------------------
__global__ void embed_kernel(const int* __restrict__ tok,
                             const float* __restrict__ emb) {
    int idx = blockIdx.x*blockDim.x + threadIdx.x;
    if (idx >= NROW*DIM) return;
    int r = idx / DIM, d = idx % DIM;
    int t = tok[r];
    float v = emb[(size_t)t*DIM + d];
    if (t != 0) v += g_sin[(r % SEQ)*DIM + d];
    g_h[(size_t)r*LDH + d] = v;
    if (d == 0) g_mask[r] = (t == 0) ? 1 : 0;
}

// ---------------- weight packing (all layers): [L,K,N] -> tf32 [L,Kp,Np] ------
__global__ void pack_w_kernel(const float* __restrict__ src, float* __restrict__ dst,
                              int K, int N, int Kp, int Np, int total) {
    int i = blockIdx.x*blockDim.x + threadIdx.x;
    if (i >= total) return;
    int per = Kp*Np;
    int l = i / per, r = i % per;
    int k = r / Np, n = r % Np;
    float v = (k < K && n < N) ? src[(size_t)l*K*N + (size_t)k*N + n] : 0.0f;
    dst[i] = to_tf32(v);
}

// ---------------- TF32 tensor-core GEMM (pipelined) ---------------------------
// C[M,N] = A[M,Kp]@Bp[Kp,Np] + bias (+gelu). A padded (cols>=K zero), no guards.
// 256 threads, 8 warps (2x4), block tile 128x128x16, warp tile 64x32.
#define BM 128
#define BN 128
#define BK 16

__global__ __launch_bounds__(256, 2) void mma_gemm_kernel(
        const float* __restrict__ A, const float* __restrict__ Bp,
        const float* __restrict__ bias, float* __restrict__ C,
        int N, int Kp, int lda, int Np, int ldc, int act) {
    __shared__ float As[2][BM][BK+4];   // stride 20: frag reads conflict-free
    __shared__ float Bs[2][BK][BN+8];   // stride 136: frag reads conflict-free

    int tid = threadIdx.x;
    int warp = tid >> 5, lane = tid & 31;
    int g = lane >> 2, tig = lane & 3;
    int mw = (warp >> 2)*64, nw = (warp & 3)*32;
    int bm = blockIdx.y*BM, bn = blockIdx.x*BN;

    const float* Abase = A + (size_t)bm*lda;
    const float* Bbase = Bp + bn;

    float acc[4][4][4];
    #pragma unroll
    for (int i = 0; i < 4; i++)
        #pragma unroll
        for (int j = 0; j < 4; j++)
            #pragma unroll
            for (int r = 0; r < 4; r++) acc[i][j][r] = 0.0f;

    int nIter = Kp / BK;

    // stage loader
    auto loadStage = [&](int it, int s) {
        int k0 = it*BK;
        #pragma unroll
        for (int t = 0; t < 2; t++) {
            int e = tid + t*256;
            int m = e >> 2, c = e & 3;
            CP16(smemu32(&As[s][m][c*4]), Abase + (size_t)m*lda + k0 + c*4);
        }
        #pragma unroll
        for (int t = 0; t < 2; t++) {
            int e = tid + t*256;
            int k = e >> 5, c = e & 31;
            CP16(smemu32(&Bs[s][k][c*4]), Bbase + (size_t)(k0+k)*Np + c*4);
        }
        CP_COMMIT();
    };

    loadStage(0, 0);

    for (int it = 0; it < nIter; it++) {
        int cur = it & 1;
        if (it + 1 < nIter) {
            loadStage(it+1, cur ^ 1);
            CP_WAIT(1);
        } else {
            CP_WAIT(0);
        }
        __syncthreads();

        #pragma unroll
        for (int ks = 0; ks < 2; ks++) {
            int kb = ks*8;
            uint32_t af[4][4], bf[4][2];
            #pragma unroll
            for (int mt = 0; mt < 4; mt++) {
                int rm = mw + mt*16;
                af[mt][0] = __float_as_uint(As[cur][rm + g    ][kb + tig    ]);
                af[mt][1] = __float_as_uint(As[cur][rm + g + 8][kb + tig    ]);
                af[mt][2] = __float_as_uint(As[cur][rm + g    ][kb + tig + 4]);
                af[mt][3] = __float_as_uint(As[cur][rm + g + 8][kb + tig + 4]);
            }
            #pragma unroll
            for (int nt = 0; nt < 4; nt++) {
                int cn = nw + nt*8;
                bf[nt][0] = __float_as_uint(Bs[cur][kb + tig    ][cn + g]);
                bf[nt][1] = __float_as_uint(Bs[cur][kb + tig + 4][cn + g]);
            }
            #pragma unroll
            for (int mt = 0; mt < 4; mt++)
                #pragma unroll
                for (int nt = 0; nt < 4; nt++) {
                    asm volatile(
                        "mma.sync.aligned.m16n8k8.row.col.f32.tf32.tf32.f32 "
                        "{%0,%1,%2,%3}, {%4,%5,%6,%7}, {%8,%9}, {%0,%1,%2,%3};"
                        : "+f"(acc[mt][nt][0]), "+f"(acc[mt][nt][1]),
                          "+f"(acc[mt][nt][2]), "+f"(acc[mt][nt][3])
                        : "r"(af[mt][0]), "r"(af[mt][1]), "r"(af[mt][2]), "r"(af[mt][3]),
                          "r"(bf[nt][0]), "r"(bf[nt][1]));
                }
        }
        __syncthreads();
    }

    // epilogue
    #pragma unroll
    for (int mt = 0; mt < 4; mt++) {
        int row0 = bm + mw + mt*16 + g;
        #pragma unroll
        for (int nt = 0; nt < 4; nt++) {
            int col = bn + nw + nt*8 + tig*2;
            if (col < N) {
                float b0 = bias[col], b1 = bias[col+1];
                float v0 = acc[mt][nt][0] + b0;
                float v1 = acc[mt][nt][1] + b1;
                float v2 = acc[mt][nt][2] + b0;
                float v3 = acc[mt][nt][3] + b1;
                if (act == 1) { v0 = gelu_f(v0); v1 = gelu_f(v1); v2 = gelu_f(v2); v3 = gelu_f(v3); }
                *(float2*)&C[(size_t)row0*ldc + col]     = make_float2(v0, v1);
                *(float2*)&C[(size_t)(row0+8)*ldc + col] = make_float2(v2, v3);
            }
        }
    }
}

// ---------------- fused attention per (b,h), K & V in smem --------------------
#define ATTN_SMEM ((2*SEQ*DHEAD + 8*SEQ)*4 + SEQ)
__global__ void attn_kernel(const float* __restrict__ qkv,
                            const unsigned char* __restrict__ mask,
                            float* __restrict__ out) {
    extern __shared__ float sm[];
    float (*Ks)[DHEAD] = (float(*)[DHEAD])sm;                     // [200][50]
    float (*Vs)[DHEAD] = (float(*)[DHEAD])(sm + SEQ*DHEAD);       // [200][50]
    float (*sc)[SEQ]   = (float(*)[SEQ])(sm + 2*SEQ*DHEAD);       // [8][200]
    unsigned char* mk  = (unsigned char*)(sm + 2*SEQ*DHEAD + 8*SEQ);

    int b = blockIdx.x / NHEAD, h = blockIdx.x % NHEAD;
    int tid = threadIdx.x, w = tid >> 5, lane = tid & 31;

    if (tid < SEQ) mk[tid] = mask[b*SEQ + tid];
    int padcnt = __syncthreads_count(tid < SEQ && mask[b*SEQ + tid]);
    bool allpad = (padcnt == SEQ);

    for (int idx = tid; idx < SEQ*DHEAD; idx += blockDim.x) {
        int s = idx / DHEAD, d = idx % DHEAD;
        Ks[s][d] = qkv[(size_t)(b*SEQ + s)*900 + 300 + h*DHEAD + d];
        Vs[s][d] = qkv[(size_t)(b*SEQ + s)*900 + 600 + h*DHEAD + d];
    }
    __syncthreads();

    const float scale = 0.1414213562373095f;  // 1/sqrt(50)

    for (int q = w; q < SEQ; q += 8) {
        const float* qp = &qkv[(size_t)(b*SEQ + q)*900 + h*DHEAD];
        float qreg[DHEAD];
        #pragma unroll
        for (int d = 0; d < DHEAD; d++) qreg[d] = qp[d];

        float smax = -INFINITY;
        for (int k = lane; k < SEQ; k += 32) {
            float s;
            if (!mk[k]) {
                s = 0.0f;
                #pragma unroll
                for (int d = 0; d < DHEAD; d++) s += qreg[d]*Ks[k][d];
                s *= scale;
                smax = fmaxf(smax, s);
            } else {
                s = -INFINITY;
            }
            sc[w][k] = s;
        }
        #pragma unroll
        for (int off = 16; off > 0; off >>= 1)
            smax = fmaxf(smax, __shfl_xor_sync(0xffffffffu, smax, off));

        float psum = 0.0f;
        __syncwarp();
        for (int k = lane; k < SEQ; k += 32) {
            float e = mk[k] ? 0.0f : expf(sc[w][k] - smax);
            sc[w][k] = e;
            psum += e;
        }
        #pragma unroll
        for (int off = 16; off > 0; off >>= 1)
            psum += __shfl_xor_sync(0xffffffffu, psum, off);
        float inv = (allpad || psum == 0.0f) ? 0.0f : 1.0f/psum;
        __syncwarp();

        for (int d = lane; d < DHEAD; d += 32) {
            float acc2 = 0.0f;
            for (int k = 0; k < SEQ; k++)
                acc2 += sc[w][k] * Vs[k][d];
            out[(size_t)(b*SEQ + q)*LDH + h*DHEAD + d] = acc2*inv;
        }
        __syncwarp();
    }
}

// ---------------- fused residual add + LayerNorm ------------------------------
__global__ void ln_kernel(const float* __restrict__ X,
                          const float* __restrict__ Y,
                          const float* __restrict__ s,
                          const float* __restrict__ bcoef,
                          float* __restrict__ out,
                          unsigned char* maskout) {
    __shared__ float red[4];
    int r = blockIdx.x, tid = threadIdx.x;   // 128 threads
    float v[3]; int nd = 0;
    float local = 0.0f;
    for (int d = tid; d < DIM; d += 128) {
        float t = X[(size_t)r*LDH + d] + Y[(size_t)r*LDH + d];
        v[nd++] = t;
        local += t;
    }
    #pragma unroll
    for (int off = 16; off > 0; off >>= 1) local += __shfl_xor_sync(0xffffffffu, local, off);
    if ((tid & 31) == 0) red[tid >> 5] = local;
    __syncthreads();
    float mean = (red[0] + red[1] + red[2] + red[3]) / (float)DIM;
    __syncthreads();

    local = 0.0f;
    for (int i = 0; i < nd; i++) { float d0 = v[i] - mean; local += d0*d0; }
    #pragma unroll
    for (int off = 16; off > 0; off >>= 1) local += __shfl_xor_sync(0xffffffffu, local, off);
    if ((tid & 31) == 0) red[tid >> 5] = local;
    __syncthreads();
    float var = (red[0] + red[1] + red[2] + red[3]) / (float)DIM;
    float rstd = 1.0f / sqrtf(var + 1e-5f);

    bool allz = true;
    int nd2 = 0;
    for (int d = tid; d < DIM; d += 128) {
        float o = (v[nd2++] - mean)*rstd*s[d] + bcoef[d];
        out[(size_t)r*LDH + d] = o;
        if (o != 0.0f) allz = false;
    }
    if (maskout) {
        int cnt = __syncthreads_count(allz ? 1 : 0);
        if (tid == 0) maskout[r] = (cnt == 128) ? 1 : 0;
    }
}

// ---------------- head kernels ------------------------------------------------
__global__ void rowdot_kernel(const float* __restrict__ w1,
                              const float* __restrict__ b1) {
    int tid = threadIdx.x, warp = tid >> 5, lane = tid & 31;
    int r = blockIdx.x*8 + warp;
    if (r >= NROW) return;
    float acc = 0.0f;
    for (int d = lane; d < DIM; d += 32)
        acc += g_h[(size_t)r*LDH + d] * w1[d];
    #pragma unroll
    for (int off = 16; off > 0; off >>= 1) acc += __shfl_xor_sync(0xffffffffu, acc, off);
    if (lane == 0) g_s1[r] = acc + b1[0];
}

__global__ void head_kernel(const float* __restrict__ w2, const float* __restrict__ b2,
                            const float* __restrict__ wo, const float* __restrict__ bo,
                            const float* __restrict__ wa, const float* __restrict__ ba,
                            float* __restrict__ out) {
    __shared__ float s1s[SEQ];
    __shared__ float s2s[50];
    int b = blockIdx.x, tid = threadIdx.x;     // 64 threads
    for (int i = tid; i < SEQ; i += 64) s1s[i] = g_s1[b*SEQ + i];
    __syncthreads();
    if (tid < 50) {
        float acc = 0.0f;
        for (int s = 0; s < SEQ; s++) acc += s1s[s]*w2[s*50 + tid];
        s2s[tid] = gelu_f(acc + b2[tid]);
    }
    __syncthreads();
    if (tid < 7) {
        float acc = 0.0f;
        if (tid == 0) {
            for (int i = 0; i < 50; i++) acc += s2s[i]*wo[i];
            out[b*7] = acc + bo[0];
        } else {
            int j = tid - 1;
            for (int i = 0; i < 50; i++) acc += s2s[i]*wa[i*6 + j];
            out[b*7 + tid] = acc + ba[j];
        }
    }
}

// ---------------- launch ------------------------------------------------------
extern "C" void kernel_launch(void* const* d_in, const int* in_sizes, int n_in,
                              void* d_out, int out_size) {
    const int*   x_tok  = (const int*)  d_in[0];
    const float* emb    = (const float*)d_in[1];
    const float* qkv_w  = (const float*)d_in[2];
    const float* qkv_b  = (const float*)d_in[3];
    const float* out_w  = (const float*)d_in[4];
    const float* out_b  = (const float*)d_in[5];
    const float* ln1_s  = (const float*)d_in[6];
    const float* ln1_b  = (const float*)d_in[7];
    const float* ff1_w  = (const float*)d_in[8];
    const float* ff1_b  = (const float*)d_in[9];
    const float* ff2_w  = (const float*)d_in[10];
    const float* ff2_b  = (const float*)d_in[11];
    const float* ln2_s  = (const float*)d_in[12];
    const float* ln2_b  = (const float*)d_in[13];
    const float* lin1_w = (const float*)d_in[14];
    const float* lin1_b = (const float*)d_in[15];
    const float* lin2_w = (const float*)d_in[16];
    const float* lin2_b = (const float*)d_in[17];
    const float* lout_w = (const float*)d_in[18];
    const float* lout_b = (const float*)d_in[19];
    const float* laux_w = (const float*)d_in[20];
    const float* laux_b = (const float*)d_in[21];

    float *p_h, *p_h1, *p_qkv, *p_att, *p_prj, *p_ff1, *p_ff2;
    float *p_wqkv, *p_wprj, *p_wff1, *p_wff2;
    unsigned char *p_mask;
    cudaGetSymbolAddress((void**)&p_h,   g_h);
    cudaGetSymbolAddress((void**)&p_h1,  g_h1);
    cudaGetSymbolAddress((void**)&p_qkv, g_qkv);
    cudaGetSymbolAddress((void**)&p_att, g_att);
    cudaGetSymbolAddress((void**)&p_prj, g_prj);
    cudaGetSymbolAddress((void**)&p_ff1, g_ff1);
    cudaGetSymbolAddress((void**)&p_ff2, g_ff2);
    cudaGetSymbolAddress((void**)&p_mask, g_mask);
    cudaGetSymbolAddress((void**)&p_wqkv, g_pw_qkv);
    cudaGetSymbolAddress((void**)&p_wprj, g_pw_prj);
    cudaGetSymbolAddress((void**)&p_wff1, g_pw_ff1);
    cudaGetSymbolAddress((void**)&p_wff2, g_pw_ff2);

    static bool attr_set = false;
    if (!attr_set) {
        cudaFuncSetAttribute(attn_kernel, cudaFuncAttributeMaxDynamicSharedMemorySize,
                             ATTN_SMEM);
        attr_set = true;
    }

    sin_table_kernel<<<(SEQ*DIM + 255)/256, 256>>>();
    embed_kernel<<<(NROW*DIM + 255)/256, 256>>>(x_tok, emb);

    // pack all layers' weights once
    pack_w_kernel<<<(5*320*1024+255)/256, 256>>>(qkv_w, p_wqkv, 300, 900, 320, 1024, 5*320*1024);
    pack_w_kernel<<<(5*320*384 +255)/256, 256>>>(out_w, p_wprj, 300, 300, 320, 384,  5*320*384);
    pack_w_kernel<<<(5*320*640 +255)/256, 256>>>(ff1_w, p_wff1, 300, 600, 320, 640,  5*320*640);
    pack_w_kernel<<<(5*608*384 +255)/256, 256>>>(ff2_w, p_wff2, 600, 300, 608, 384,  5*608*384);

    for (int l = 0; l < 5; l++) {
        // QKV: A[51200,320] @ B[320,1024] -> C stride 900, N=900
        mma_gemm_kernel<<<dim3(8, NROW/BM), 256>>>(p_h, p_wqkv + (size_t)l*320*1024,
            qkv_b + l*900, p_qkv, 900, 320, LDH, 1024, 900, 0);
        attn_kernel<<<BATCH*NHEAD, 256, ATTN_SMEM>>>(p_qkv, p_mask, p_att);
        // out proj: N=300
        mma_gemm_kernel<<<dim3(3, NROW/BM), 256>>>(p_att, p_wprj + (size_t)l*320*384,
            out_b + l*DIM, p_prj, 300, 320, LDH, 384, LDH, 0);
        ln_kernel<<<NROW, 128>>>(p_h, p_prj, ln1_s + l*DIM, ln1_b + l*DIM, p_h1, nullptr);
        // FF1 + gelu: N=600, C stride 608
        mma_gemm_kernel<<<dim3(5, NROW/BM), 256>>>(p_h1, p_wff1 + (size_t)l*320*640,
            ff1_b + l*2*DIM, p_ff1, 600, 320, LDH, 640, LDF, 1);
        // FF2: K=608, N=300
        mma_gemm_kernel<<<dim3(3, NROW/BM), 256>>>(p_ff1, p_wff2 + (size_t)l*608*384,
            ff2_b + l*DIM, p_ff2, 300, 608, LDF, 384, LDH, 0);
        ln_kernel<<<NROW, 128>>>(p_h1, p_ff2, ln2_s + l*DIM, ln2_b + l*DIM, p_h, p_mask);
    }

    rowdot_kernel<<<NROW/8, 256>>>(lin1_w, lin1_b);
    head_kernel<<<BATCH, 64>>>(lin2_w, lin2_b, lout_w, lout_b, laux_w, laux_b,
                               (float*)d_out);
}

// round 6
// speedup vs baseline: 2.2411x; 1.0135x over previous
#include <cuda_runtime.h>
#include <math.h>
#include <stdint.h>

// Problem constants
#define BATCH 256
#define SEQ   200
#define DIM   300
#define NHEAD 6
#define DHEAD 50
#define NROW  (BATCH*SEQ)        // 51200
#define LDH   320                // padded stride for D=300 activations
#define LDF   608                // padded stride for 600-dim FF hidden
#define GELU_C 0.7978845608028654f

// ---------------- scratch (device globals; zero-initialized) ------------------
__device__ float g_sin[SEQ*DIM];
__device__ float g_h  [NROW*LDH];
__device__ float g_h1 [NROW*LDH];
__device__ float g_qkv[NROW*900];
__device__ float g_att[NROW*LDH];
__device__ float g_prj[NROW*LDH];
__device__ float g_ff1[NROW*LDF];
__device__ float g_ff2[NROW*LDH];
__device__ float g_s1 [NROW];
__device__ unsigned char g_mask[NROW];

// packed tf32 weights, all 5 layers, zero padded to Kp x Np
__device__ float g_pw_qkv[5*320*1024];
__device__ float g_pw_prj[5*320*384];
__device__ float g_pw_ff1[5*320*640];
__device__ float g_pw_ff2[5*608*384];

__device__ __forceinline__ float gelu_f(float x) {
    float x3 = x*x*x;
    return 0.5f*x*(1.0f + tanhf(GELU_C*(x + 0.044715f*x3)));
}
__device__ __forceinline__ float to_tf32(float v) {
    uint32_t t;
    asm("cvt.rna.tf32.f32 %0, %1;" : "=r"(t) : "f"(v));
    return __uint_as_float(t);
}
__device__ __forceinline__ uint32_t smemu32(const void* p) {
    return (uint32_t)__cvta_generic_to_shared(p);
}
#define CP16(dst, src) asm volatile("cp.async.cg.shared.global [%0], [%1], 16;\n" :: "r"(dst), "l"(src))
#define CP_COMMIT()    asm volatile("cp.async.commit_group;\n" ::)
#define CP_WAIT(N)     asm volatile("cp.async.wait_group %0;\n" :: "n"(N))

// ---------------- sinusoid table ----------------------------------------------
__global__ void sin_table_kernel() {
    int idx = blockIdx.x*blockDim.x + threadIdx.x;
    if (idx >= SEQ*DIM) return;
    int pos = idx / DIM, i = idx % DIM;
    double ang = (double)pos / pow(10000.0, 2.0*(double)(i/2)/(double)DIM);
    g_sin[idx] = (float)((i & 1) ? cos(ang) : sin(ang));
}

// ---------------- embedding + pos-enc + initial mask --------------------------
__global__ void embed_kernel(const int* __restrict__ tok,
                             const float* __restrict__ emb) {
    int idx = blockIdx.x*blockDim.x + threadIdx.x;
    if (idx >= NROW*DIM) return;
    int r = idx / DIM, d = idx % DIM;
    int t = tok[r];
    float v = emb[(size_t)t*DIM + d];
    if (t != 0) v += g_sin[(r % SEQ)*DIM + d];
    g_h[(size_t)r*LDH + d] = v;
    if (d == 0) g_mask[r] = (t == 0) ? 1 : 0;
}

// ---------------- merged weight packing (all 4 weights, all 5 layers) ---------
#define PK_S1 (5*320*1024)
#define PK_S2 (5*320*384)
#define PK_S3 (5*320*640)
#define PK_S4 (5*608*384)
__device__ __forceinline__ void pack_one(const float* __restrict__ src,
                                         float* __restrict__ dst, int i,
                                         int K, int N, int Kp, int Np) {
    int per = Kp*Np;
    int l = i / per, r = i % per;
    int k = r / Np, n = r % Np;
    float v = (k < K && n < N) ? src[(size_t)l*K*N + (size_t)k*N + n] : 0.0f;
    dst[i] = to_tf32(v);
}
__global__ void pack_all_kernel(const float* __restrict__ qkv_w,
                                const float* __restrict__ out_w,
                                const float* __restrict__ ff1_w,
                                const float* __restrict__ ff2_w) {
    int i = blockIdx.x*blockDim.x + threadIdx.x;
    if (i < PK_S1) { pack_one(qkv_w, g_pw_qkv, i, 300, 900, 320, 1024); return; }
    i -= PK_S1;
    if (i < PK_S2) { pack_one(out_w, g_pw_prj, i, 300, 300, 320, 384); return; }
    i -= PK_S2;
    if (i < PK_S3) { pack_one(ff1_w, g_pw_ff1, i, 300, 600, 320, 640); return; }
    i -= PK_S3;
    if (i < PK_S4) { pack_one(ff2_w, g_pw_ff2, i, 600, 300, 608, 384); return; }
}

// ---------------- TF32 tensor-core GEMM (4-stage pipeline) --------------------
// C[M,N] = A[M,Kp]@Bp[Kp,Np] + bias (+gelu). A padded (cols>=K zero), no guards.
// 256 threads, 8 warps (2x4), block tile 128x128x16, warp tile 64x32.
#define BM 128
#define BN 128
#define BK 16
#define STAGES 4
#define ASTRIDE 20
#define BSTRIDE 136
#define A_ELEMS (BM*ASTRIDE)            // per stage
#define B_ELEMS (BK*BSTRIDE)
#define GEMM_SMEM ((STAGES*(A_ELEMS + B_ELEMS))*4)   // 75776 bytes

__global__ __launch_bounds__(256, 2) void mma_gemm_kernel(
        const float* __restrict__ A, const float* __restrict__ Bp,
        const float* __restrict__ bias, float* __restrict__ C,
        int N, int Kp, int lda, int Np, int ldc, int act) {
    extern __shared__ float dsm[];
    float* Asm = dsm;                         // [STAGES][BM][ASTRIDE]
    float* Bsm = dsm + STAGES*A_ELEMS;        // [STAGES][BK][BSTRIDE]

    int tid = threadIdx.x;
    int warp = tid >> 5, lane = tid & 31;
    int g = lane >> 2, tig = lane & 3;
    int mw = (warp >> 2)*64, nw = (warp & 3)*32;
    int bm = blockIdx.y*BM, bn = blockIdx.x*BN;

    const float* Abase = A + (size_t)bm*lda;
    const float* Bbase = Bp + bn;

    float acc[4][4][4];
    #pragma unroll
    for (int i = 0; i < 4; i++)
        #pragma unroll
        for (int j = 0; j < 4; j++)
            #pragma unroll
            for (int r = 0; r < 4; r++) acc[i][j][r] = 0.0f;

    int nIter = Kp / BK;

    // per-thread load coords (fixed)
    int am0 = tid >> 2,            ac0 = (tid & 3)*4;
    int am1 = (tid + 256) >> 2,    ac1 = ac0;
    int bk0 = tid >> 5,            bc0 = (tid & 31)*4;
    int bk1 = (tid + 256) >> 5,    bc1 = bc0;

    auto loadStage = [&](int it, int s) {
        int k0 = it*BK;
        float* As = Asm + s*A_ELEMS;
        float* Bs = Bsm + s*B_ELEMS;
        CP16(smemu32(&As[am0*ASTRIDE + ac0]), Abase + (size_t)am0*lda + k0 + ac0);
        CP16(smemu32(&As[am1*ASTRIDE + ac1]), Abase + (size_t)am1*lda + k0 + ac1);
        CP16(smemu32(&Bs[bk0*BSTRIDE + bc0]), Bbase + (size_t)(k0+bk0)*Np + bc0);
        CP16(smemu32(&Bs[bk1*BSTRIDE + bc1]), Bbase + (size_t)(k0+bk1)*Np + bc1);
    };

    // prologue: fill 3 stages
    #pragma unroll
    for (int s = 0; s < STAGES-1; s++) {
        loadStage(s, s);
        CP_COMMIT();
    }

    for (int it = 0; it < nIter; it++) {
        int cur = it & (STAGES-1);
        __syncthreads();                     // all warps done with stage (it-1) slot
        if (it + STAGES-1 < nIter)
            loadStage(it + STAGES-1, (it + STAGES-1) & (STAGES-1));
        CP_COMMIT();
        CP_WAIT(STAGES-1);                   // stage `it` group complete
        __syncthreads();

        const float* As = Asm + cur*A_ELEMS;
        const float* Bs = Bsm + cur*B_ELEMS;
        #pragma unroll
        for (int ks = 0; ks < 2; ks++) {
            int kb = ks*8;
            uint32_t af[4][4], bf[4][2];
            #pragma unroll
            for (int mt = 0; mt < 4; mt++) {
                int rm = mw + mt*16;
                af[mt][0] = __float_as_uint(As[(rm + g    )*ASTRIDE + kb + tig    ]);
                af[mt][1] = __float_as_uint(As[(rm + g + 8)*ASTRIDE + kb + tig    ]);
                af[mt][2] = __float_as_uint(As[(rm + g    )*ASTRIDE + kb + tig + 4]);
                af[mt][3] = __float_as_uint(As[(rm + g + 8)*ASTRIDE + kb + tig + 4]);
            }
            #pragma unroll
            for (int nt = 0; nt < 4; nt++) {
                int cn = nw + nt*8;
                bf[nt][0] = __float_as_uint(Bs[(kb + tig    )*BSTRIDE + cn + g]);
                bf[nt][1] = __float_as_uint(Bs[(kb + tig + 4)*BSTRIDE + cn + g]);
            }
            #pragma unroll
            for (int mt = 0; mt < 4; mt++)
                #pragma unroll
                for (int nt = 0; nt < 4; nt++) {
                    asm volatile(
                        "mma.sync.aligned.m16n8k8.row.col.f32.tf32.tf32.f32 "
                        "{%0,%1,%2,%3}, {%4,%5,%6,%7}, {%8,%9}, {%0,%1,%2,%3};"
                        : "+f"(acc[mt][nt][0]), "+f"(acc[mt][nt][1]),
                          "+f"(acc[mt][nt][2]), "+f"(acc[mt][nt][3])
                        : "r"(af[mt][0]), "r"(af[mt][1]), "r"(af[mt][2]), "r"(af[mt][3]),
                          "r"(bf[nt][0]), "r"(bf[nt][1]));
                }
        }
    }

    // epilogue
    #pragma unroll
    for (int mt = 0; mt < 4; mt++) {
        int row0 = bm + mw + mt*16 + g;
        #pragma unroll
        for (int nt = 0; nt < 4; nt++) {
            int col = bn + nw + nt*8 + tig*2;
            if (col < N) {
                float b0 = bias[col], b1 = bias[col+1];
                float v0 = acc[mt][nt][0] + b0;
                float v1 = acc[mt][nt][1] + b1;
                float v2 = acc[mt][nt][2] + b0;
                float v3 = acc[mt][nt][3] + b1;
                if (act == 1) { v0 = gelu_f(v0); v1 = gelu_f(v1); v2 = gelu_f(v2); v3 = gelu_f(v3); }
                *(float2*)&C[(size_t)row0*ldc + col]     = make_float2(v0, v1);
                *(float2*)&C[(size_t)(row0+8)*ldc + col] = make_float2(v2, v3);
            }
        }
    }
}

// ---------------- fused attention per (b,h), K & V in smem --------------------
#define ATTN_SMEM ((2*SEQ*DHEAD + 8*SEQ)*4 + SEQ)
__global__ void attn_kernel(const float* __restrict__ qkv,
                            const unsigned char* __restrict__ mask,
                            float* __restrict__ out) {
    extern __shared__ float sm[];
    float (*Ks)[DHEAD] = (float(*)[DHEAD])sm;                     // [200][50]
    float (*Vs)[DHEAD] = (float(*)[DHEAD])(sm + SEQ*DHEAD);       // [200][50]
    float (*sc)[SEQ]   = (float(*)[SEQ])(sm + 2*SEQ*DHEAD);       // [8][200]
    unsigned char* mk  = (unsigned char*)(sm + 2*SEQ*DHEAD + 8*SEQ);

    int b = blockIdx.x / NHEAD, h = blockIdx.x % NHEAD;
    int tid = threadIdx.x, w = tid >> 5, lane = tid & 31;

    if (tid < SEQ) mk[tid] = mask[b*SEQ + tid];
    int padcnt = __syncthreads_count(tid < SEQ && mask[b*SEQ + tid]);
    bool allpad = (padcnt == SEQ);

    for (int idx = tid; idx < SEQ*DHEAD; idx += blockDim.x) {
        int s = idx / DHEAD, d = idx % DHEAD;
        Ks[s][d] = qkv[(size_t)(b*SEQ + s)*900 + 300 + h*DHEAD + d];
        Vs[s][d] = qkv[(size_t)(b*SEQ + s)*900 + 600 + h*DHEAD + d];
    }
    __syncthreads();

    const float scale = 0.1414213562373095f;  // 1/sqrt(50)

    for (int q = w; q < SEQ; q += 8) {
        const float* qp = &qkv[(size_t)(b*SEQ + q)*900 + h*DHEAD];
        float qreg[DHEAD];
        #pragma unroll
        for (int d = 0; d < DHEAD; d++) qreg[d] = qp[d];

        float smax = -INFINITY;
        for (int k = lane; k < SEQ; k += 32) {
            float s;
            if (!mk[k]) {
                s = 0.0f;
                #pragma unroll
                for (int d = 0; d < DHEAD; d++) s += qreg[d]*Ks[k][d];
                s *= scale;
                smax = fmaxf(smax, s);
            } else {
                s = -INFINITY;
            }
            sc[w][k] = s;
        }
        #pragma unroll
        for (int off = 16; off > 0; off >>= 1)
            smax = fmaxf(smax, __shfl_xor_sync(0xffffffffu, smax, off));

        float psum = 0.0f;
        __syncwarp();
        for (int k = lane; k < SEQ; k += 32) {
            float e = mk[k] ? 0.0f : expf(sc[w][k] - smax);
            sc[w][k] = e;
            psum += e;
        }
        #pragma unroll
        for (int off = 16; off > 0; off >>= 1)
            psum += __shfl_xor_sync(0xffffffffu, psum, off);
        float inv = (allpad || psum == 0.0f) ? 0.0f : 1.0f/psum;
        __syncwarp();

        for (int d = lane; d < DHEAD; d += 32) {
            float acc2 = 0.0f;
            for (int k = 0; k < SEQ; k++)
                acc2 += sc[w][k] * Vs[k][d];
            out[(size_t)(b*SEQ + q)*LDH + h*DHEAD + d] = acc2*inv;
        }
        __syncwarp();
    }
}

// ---------------- fused residual add + LayerNorm ------------------------------
__global__ void ln_kernel(const float* __restrict__ X,
                          const float* __restrict__ Y,
                          const float* __restrict__ s,
                          const float* __restrict__ bcoef,
                          float* __restrict__ out,
                          unsigned char* maskout) {
    __shared__ float red[4];
    int r = blockIdx.x, tid = threadIdx.x;   // 128 threads
    float v[3]; int nd = 0;
    float local = 0.0f;
    for (int d = tid; d < DIM; d += 128) {
        float t = X[(size_t)r*LDH + d] + Y[(size_t)r*LDH + d];
        v[nd++] = t;
        local += t;
    }
    #pragma unroll
    for (int off = 16; off > 0; off >>= 1) local += __shfl_xor_sync(0xffffffffu, local, off);
    if ((tid & 31) == 0) red[tid >> 5] = local;
    __syncthreads();
    float mean = (red[0] + red[1] + red[2] + red[3]) / (float)DIM;
    __syncthreads();

    local = 0.0f;
    for (int i = 0; i < nd; i++) { float d0 = v[i] - mean; local += d0*d0; }
    #pragma unroll
    for (int off = 16; off > 0; off >>= 1) local += __shfl_xor_sync(0xffffffffu, local, off);
    if ((tid & 31) == 0) red[tid >> 5] = local;
    __syncthreads();
    float var = (red[0] + red[1] + red[2] + red[3]) / (float)DIM;
    float rstd = 1.0f / sqrtf(var + 1e-5f);

    bool allz = true;
    int nd2 = 0;
    for (int d = tid; d < DIM; d += 128) {
        float o = (v[nd2++] - mean)*rstd*s[d] + bcoef[d];
        out[(size_t)r*LDH + d] = o;
        if (o != 0.0f) allz = false;
    }
    if (maskout) {
        int cnt = __syncthreads_count(allz ? 1 : 0);
        if (tid == 0) maskout[r] = (cnt == 128) ? 1 : 0;
    }
}

// ---------------- head kernels ------------------------------------------------
__global__ void rowdot_kernel(const float* __restrict__ w1,
                              const float* __restrict__ b1) {
    int tid = threadIdx.x, warp = tid >> 5, lane = tid & 31;
    int r = blockIdx.x*8 + warp;
    if (r >= NROW) return;
    float acc = 0.0f;
    for (int d = lane; d < DIM; d += 32)
        acc += g_h[(size_t)r*LDH + d] * w1[d];
    #pragma unroll
    for (int off = 16; off > 0; off >>= 1) acc += __shfl_xor_sync(0xffffffffu, acc, off);
    if (lane == 0) g_s1[r] = acc + b1[0];
}

__global__ void head_kernel(const float* __restrict__ w2, const float* __restrict__ b2,
                            const float* __restrict__ wo, const float* __restrict__ bo,
                            const float* __restrict__ wa, const float* __restrict__ ba,
                            float* __restrict__ out) {
    __shared__ float s1s[SEQ];
    __shared__ float s2s[50];
    int b = blockIdx.x, tid = threadIdx.x;     // 64 threads
    for (int i = tid; i < SEQ; i += 64) s1s[i] = g_s1[b*SEQ + i];
    __syncthreads();
    if (tid < 50) {
        float acc = 0.0f;
        for (int s = 0; s < SEQ; s++) acc += s1s[s]*w2[s*50 + tid];
        s2s[tid] = gelu_f(acc + b2[tid]);
    }
    __syncthreads();
    if (tid < 7) {
        float acc = 0.0f;
        if (tid == 0) {
            for (int i = 0; i < 50; i++) acc += s2s[i]*wo[i];
            out[b*7] = acc + bo[0];
        } else {
            int j = tid - 1;
            for (int i = 0; i < 50; i++) acc += s2s[i]*wa[i*6 + j];
            out[b*7 + tid] = acc + ba[j];
        }
    }
}

// ---------------- launch ------------------------------------------------------
extern "C" void kernel_launch(void* const* d_in, const int* in_sizes, int n_in,
                              void* d_out, int out_size) {
    const int*   x_tok  = (const int*)  d_in[0];
    const float* emb    = (const float*)d_in[1];
    const float* qkv_w  = (const float*)d_in[2];
    const float* qkv_b  = (const float*)d_in[3];
    const float* out_w  = (const float*)d_in[4];
    const float* out_b  = (const float*)d_in[5];
    const float* ln1_s  = (const float*)d_in[6];
    const float* ln1_b  = (const float*)d_in[7];
    const float* ff1_w  = (const float*)d_in[8];
    const float* ff1_b  = (const float*)d_in[9];
    const float* ff2_w  = (const float*)d_in[10];
    const float* ff2_b  = (const float*)d_in[11];
    const float* ln2_s  = (const float*)d_in[12];
    const float* ln2_b  = (const float*)d_in[13];
    const float* lin1_w = (const float*)d_in[14];
    const float* lin1_b = (const float*)d_in[15];
    const float* lin2_w = (const float*)d_in[16];
    const float* lin2_b = (const float*)d_in[17];
    const float* lout_w = (const float*)d_in[18];
    const float* lout_b = (const float*)d_in[19];
    const float* laux_w = (const float*)d_in[20];
    const float* laux_b = (const float*)d_in[21];

    float *p_h, *p_h1, *p_qkv, *p_att, *p_prj, *p_ff1, *p_ff2;
    float *p_wqkv, *p_wprj, *p_wff1, *p_wff2;
    unsigned char *p_mask;
    cudaGetSymbolAddress((void**)&p_h,   g_h);
    cudaGetSymbolAddress((void**)&p_h1,  g_h1);
    cudaGetSymbolAddress((void**)&p_qkv, g_qkv);
    cudaGetSymbolAddress((void**)&p_att, g_att);
    cudaGetSymbolAddress((void**)&p_prj, g_prj);
    cudaGetSymbolAddress((void**)&p_ff1, g_ff1);
    cudaGetSymbolAddress((void**)&p_ff2, g_ff2);
    cudaGetSymbolAddress((void**)&p_mask, g_mask);
    cudaGetSymbolAddress((void**)&p_wqkv, g_pw_qkv);
    cudaGetSymbolAddress((void**)&p_wprj, g_pw_prj);
    cudaGetSymbolAddress((void**)&p_wff1, g_pw_ff1);
    cudaGetSymbolAddress((void**)&p_wff2, g_pw_ff2);

    cudaFuncSetAttribute(attn_kernel, cudaFuncAttributeMaxDynamicSharedMemorySize,
                         ATTN_SMEM);
    cudaFuncSetAttribute(mma_gemm_kernel, cudaFuncAttributeMaxDynamicSharedMemorySize,
                         GEMM_SMEM);

    sin_table_kernel<<<(SEQ*DIM + 255)/256, 256>>>();
    embed_kernel<<<(NROW*DIM + 255)/256, 256>>>(x_tok, emb);
    pack_all_kernel<<<(PK_S1+PK_S2+PK_S3+PK_S4+255)/256, 256>>>(qkv_w, out_w, ff1_w, ff2_w);

    for (int l = 0; l < 5; l++) {
        // QKV: A[51200,320] @ B[320,1024] -> C stride 900, N=900
        mma_gemm_kernel<<<dim3(8, NROW/BM), 256, GEMM_SMEM>>>(p_h, p_wqkv + (size_t)l*320*1024,
            qkv_b + l*900, p_qkv, 900, 320, LDH, 1024, 900, 0);
        attn_kernel<<<BATCH*NHEAD, 256, ATTN_SMEM>>>(p_qkv, p_mask, p_att);
        // out proj: N=300
        mma_gemm_kernel<<<dim3(3, NROW/BM), 256, GEMM_SMEM>>>(p_att, p_wprj + (size_t)l*320*384,
            out_b + l*DIM, p_prj, 300, 320, LDH, 384, LDH, 0);
        ln_kernel<<<NROW, 128>>>(p_h, p_prj, ln1_s + l*DIM, ln1_b + l*DIM, p_h1, nullptr);
        // FF1 + gelu: N=600, C stride 608
        mma_gemm_kernel<<<dim3(5, NROW/BM), 256, GEMM_SMEM>>>(p_h1, p_wff1 + (size_t)l*320*640,
            ff1_b + l*2*DIM, p_ff1, 600, 320, LDH, 640, LDF, 1);
        // FF2: K=608, N=300
        mma_gemm_kernel<<<dim3(3, NROW/BM), 256, GEMM_SMEM>>>(p_ff1, p_wff2 + (size_t)l*608*384,
            ff2_b + l*DIM, p_ff2, 300, 608, LDF, 384, LDH, 0);
        ln_kernel<<<NROW, 128>>>(p_h1, p_ff2, ln2_s + l*DIM, ln2_b + l*DIM, p_h, p_mask);
    }

    rowdot_kernel<<<NROW/8, 256>>>(lin1_w, lin1_b);
    head_kernel<<<BATCH, 64>>>(lin2_w, lin2_b, lout_w, lout_b, laux_w, laux_b,
                               (float*)d_out);
}

// round 8
// speedup vs baseline: 3.1113x; 1.3883x over previous
#include <cuda_runtime.h>
#include <math.h>
#include <stdint.h>

// Problem constants
#define BATCH 256
#define SEQ   200
#define DIM   300
#define NHEAD 6
#define DHEAD 50
#define NROW  (BATCH*SEQ)        // 51200
#define LDH   320                // padded stride for D=300 activations
#define LDF   608                // padded stride for 600-dim FF hidden
#define GELU_C 0.7978845608028654f

// ---------------- scratch (device globals; zero-initialized) ------------------
__device__ float g_sin[SEQ*DIM];
__device__ float g_h  [NROW*LDH];
__device__ float g_h1 [NROW*LDH];
__device__ float g_qkv[NROW*900];
__device__ float g_att[NROW*LDH];
__device__ float g_prj[NROW*LDH];
__device__ float g_ff1[NROW*LDF];
__device__ float g_ff2[NROW*LDH];
__device__ float g_s1 [NROW];
__device__ unsigned char g_mask[NROW];

// packed tf32 weights, all 5 layers, zero padded to Kp x Np
__device__ float g_pw_qkv[5*320*1024];
__device__ float g_pw_prj[5*320*384];
__device__ float g_pw_ff1[5*320*640];
__device__ float g_pw_ff2[5*608*384];

__device__ __forceinline__ float gelu_f(float x) {
    float x3 = x*x*x;
    return 0.5f*x*(1.0f + tanhf(GELU_C*(x + 0.044715f*x3)));
}
__device__ __forceinline__ float to_tf32(float v) {
    uint32_t t;
    asm("cvt.rna.tf32.f32 %0, %1;" : "=r"(t) : "f"(v));
    return __uint_as_float(t);
}
__device__ __forceinline__ uint32_t smemu32(const void* p) {
    return (uint32_t)__cvta_generic_to_shared(p);
}
#define CP16(dst, src) asm volatile("cp.async.cg.shared.global [%0], [%1], 16;\n" :: "r"(dst), "l"(src))
#define CP_COMMIT()    asm volatile("cp.async.commit_group;\n" ::)
#define CP_WAIT(N)     asm volatile("cp.async.wait_group %0;\n" :: "n"(N))

#define MMA_TF32(acc, a0,a1,a2,a3, b0,b1) \
    asm volatile( \
        "mma.sync.aligned.m16n8k8.row.col.f32.tf32.tf32.f32 " \
        "{%0,%1,%2,%3}, {%4,%5,%6,%7}, {%8,%9}, {%0,%1,%2,%3};" \
        : "+f"((acc)[0]), "+f"((acc)[1]), "+f"((acc)[2]), "+f"((acc)[3]) \
        : "r"(a0), "r"(a1), "r"(a2), "r"(a3), "r"(b0), "r"(b1))

// ---------------- sinusoid table ----------------------------------------------
__global__ void sin_table_kernel() {
    int idx = blockIdx.x*blockDim.x + threadIdx.x;
    if (idx >= SEQ*DIM) return;
    int pos = idx / DIM, i = idx % DIM;
    double ang = (double)pos / pow(10000.0, 2.0*(double)(i/2)/(double)DIM);
    g_sin[idx] = (float)((i & 1) ? cos(ang) : sin(ang));
}

// ---------------- embedding + pos-enc + initial mask --------------------------
__global__ void embed_kernel(const int* __restrict__ tok,
                             const float* __restrict__ emb) {
    int idx = blockIdx.x*blockDim.x + threadIdx.x;
    if (idx >= NROW*DIM) return;
    int r = idx / DIM, d = idx % DIM;
    int t = tok[r];
    float v = emb[(size_t)t*DIM + d];
    if (t != 0) v += g_sin[(r % SEQ)*DIM + d];
    g_h[(size_t)r*LDH + d] = v;
    if (d == 0) g_mask[r] = (t == 0) ? 1 : 0;
}

// ---------------- merged weight packing (all 4 weights, all 5 layers) ---------
#define PK_S1 (5*320*1024)
#define PK_S2 (5*320*384)
#define PK_S3 (5*320*640)
#define PK_S4 (5*608*384)
__device__ __forceinline__ void pack_one(const float* __restrict__ src,
                                         float* __restrict__ dst, int i,
                                         int K, int N, int Kp, int Np) {
    int per = Kp*Np;
    int l = i / per, r = i % per;
    int k = r / Np, n = r % Np;
    float v = (k < K && n < N) ? src[(size_t)l*K*N + (size_t)k*N + n] : 0.0f;
    dst[i] = to_tf32(v);
}
__global__ void pack_all_kernel(const float* __restrict__ qkv_w,
                                const float* __restrict__ out_w,
                                const float* __restrict__ ff1_w,
                                const float* __restrict__ ff2_w) {
    int i = blockIdx.x*blockDim.x + threadIdx.x;
    if (i < PK_S1) { pack_one(qkv_w, g_pw_qkv, i, 300, 900, 320, 1024); return; }
    i -= PK_S1;
    if (i < PK_S2) { pack_one(out_w, g_pw_prj, i, 300, 300, 320, 384); return; }
    i -= PK_S2;
    if (i < PK_S3) { pack_one(ff1_w, g_pw_ff1, i, 300, 600, 320, 640); return; }
    i -= PK_S3;
    if (i < PK_S4) { pack_one(ff2_w, g_pw_ff2, i, 600, 300, 608, 384); return; }
}

// ---------------- TF32 tensor-core GEMM (4-stage pipeline) --------------------
#define BM 128
#define BN 128
#define BK 16
#define STAGES 4
#define ASTRIDE 20
#define BSTRIDE 136
#define A_ELEMS (BM*ASTRIDE)
#define B_ELEMS (BK*BSTRIDE)
#define GEMM_SMEM ((STAGES*(A_ELEMS + B_ELEMS))*4)   // 75776 bytes

__global__ __launch_bounds__(256, 2) void mma_gemm_kernel(
        const float* __restrict__ A, const float* __restrict__ Bp,
        const float* __restrict__ bias, float* __restrict__ C,
        int N, int Kp, int lda, int Np, int ldc, int act) {
    extern __shared__ float dsm[];
    float* Asm = dsm;
    float* Bsm = dsm + STAGES*A_ELEMS;

    int tid = threadIdx.x;
    int warp = tid >> 5, lane = tid & 31;
    int g = lane >> 2, tig = lane & 3;
    int mw = (warp >> 2)*64, nw = (warp & 3)*32;
    int bm = blockIdx.y*BM, bn = blockIdx.x*BN;

    const float* Abase = A + (size_t)bm*lda;
    const float* Bbase = Bp + bn;

    float acc[4][4][4];
    #pragma unroll
    for (int i = 0; i < 4; i++)
        #pragma unroll
        for (int j = 0; j < 4; j++)
            #pragma unroll
            for (int r = 0; r < 4; r++) acc[i][j][r] = 0.0f;

    int nIter = Kp / BK;

    int am0 = tid >> 2,            ac0 = (tid & 3)*4;
    int am1 = (tid + 256) >> 2,    ac1 = ac0;
    int bk0 = tid >> 5,            bc0 = (tid & 31)*4;
    int bk1 = (tid + 256) >> 5,    bc1 = bc0;

    auto loadStage = [&](int it, int s) {
        int k0 = it*BK;
        float* As = Asm + s*A_ELEMS;
        float* Bs = Bsm + s*B_ELEMS;
        CP16(smemu32(&As[am0*ASTRIDE + ac0]), Abase + (size_t)am0*lda + k0 + ac0);
        CP16(smemu32(&As[am1*ASTRIDE + ac1]), Abase + (size_t)am1*lda + k0 + ac1);
        CP16(smemu32(&Bs[bk0*BSTRIDE + bc0]), Bbase + (size_t)(k0+bk0)*Np + bc0);
        CP16(smemu32(&Bs[bk1*BSTRIDE + bc1]), Bbase + (size_t)(k0+bk1)*Np + bc1);
    };

    #pragma unroll
    for (int s = 0; s < STAGES-1; s++) {
        loadStage(s, s);
        CP_COMMIT();
    }

    for (int it = 0; it < nIter; it++) {
        int cur = it & (STAGES-1);
        __syncthreads();
        if (it + STAGES-1 < nIter)
            loadStage(it + STAGES-1, (it + STAGES-1) & (STAGES-1));
        CP_COMMIT();
        CP_WAIT(STAGES-1);
        __syncthreads();

        const float* As = Asm + cur*A_ELEMS;
        const float* Bs = Bsm + cur*B_ELEMS;
        #pragma unroll
        for (int ks = 0; ks < 2; ks++) {
            int kb = ks*8;
            uint32_t af[4][4], bf[4][2];
            #pragma unroll
            for (int mt = 0; mt < 4; mt++) {
                int rm = mw + mt*16;
                af[mt][0] = __float_as_uint(As[(rm + g    )*ASTRIDE + kb + tig    ]);
                af[mt][1] = __float_as_uint(As[(rm + g + 8)*ASTRIDE + kb + tig    ]);
                af[mt][2] = __float_as_uint(As[(rm + g    )*ASTRIDE + kb + tig + 4]);
                af[mt][3] = __float_as_uint(As[(rm + g + 8)*ASTRIDE + kb + tig + 4]);
            }
            #pragma unroll
            for (int nt = 0; nt < 4; nt++) {
                int cn = nw + nt*8;
                bf[nt][0] = __float_as_uint(Bs[(kb + tig    )*BSTRIDE + cn + g]);
                bf[nt][1] = __float_as_uint(Bs[(kb + tig + 4)*BSTRIDE + cn + g]);
            }
            #pragma unroll
            for (int mt = 0; mt < 4; mt++)
                #pragma unroll
                for (int nt = 0; nt < 4; nt++)
                    MMA_TF32(acc[mt][nt], af[mt][0], af[mt][1], af[mt][2], af[mt][3],
                             bf[nt][0], bf[nt][1]);
        }
    }

    #pragma unroll
    for (int mt = 0; mt < 4; mt++) {
        int row0 = bm + mw + mt*16 + g;
        #pragma unroll
        for (int nt = 0; nt < 4; nt++) {
            int col = bn + nw + nt*8 + tig*2;
            if (col < N) {
                float b0 = bias[col], b1 = bias[col+1];
                float v0 = acc[mt][nt][0] + b0;
                float v1 = acc[mt][nt][1] + b1;
                float v2 = acc[mt][nt][2] + b0;
                float v3 = acc[mt][nt][3] + b1;
                if (act == 1) { v0 = gelu_f(v0); v1 = gelu_f(v1); v2 = gelu_f(v2); v3 = gelu_f(v3); }
                *(float2*)&C[(size_t)row0*ldc + col]     = make_float2(v0, v1);
                *(float2*)&C[(size_t)(row0+8)*ldc + col] = make_float2(v2, v3);
            }
        }
    }
}

// ---------------- tensor-core attention, one block per (b,h) ------------------
// Smem strides chosen so all mma fragment reads are bank-conflict-free
// (stride mod 32 in {4,8,20,24} patterns verified per-lane).
#define KT_STRIDE 216     // Kt[64][216]  (d-major, k columns)
#define VS_STRIDE 72      // Vs[208][72]  (k-major, d columns)
#define QS_STRIDE 68      // Qs[64][68]
#define PS_STRIDE 212     // Ps[64][212]  (scores / probabilities)
#define KT_ELEMS (64*KT_STRIDE)
#define VS_ELEMS (208*VS_STRIDE)
#define QS_ELEMS (64*QS_STRIDE)
#define PS_ELEMS (64*PS_STRIDE)
#define ATTN_SMEM ((KT_ELEMS + VS_ELEMS + QS_ELEMS + PS_ELEMS + 64)*4 + 256)

__global__ __launch_bounds__(256) void attn_kernel(
        const float* __restrict__ qkv,
        const unsigned char* __restrict__ mask,
        float* __restrict__ out) {
    extern __shared__ float sm[];
    float* Kt  = sm;
    float* Vs  = Kt + KT_ELEMS;
    float* Qs  = Vs + VS_ELEMS;
    float* Ps  = Qs + QS_ELEMS;
    float* inv = Ps + PS_ELEMS;
    unsigned char* mk = (unsigned char*)(inv + 64);

    int b = blockIdx.x / NHEAD, h = blockIdx.x % NHEAD;
    int tid = threadIdx.x;
    int warp = tid >> 5, lane = tid & 31;
    int g = lane >> 2, tig = lane & 3;
    int wm = (warp >> 1)*16;          // row base within 64-row chunk
    int wn = warp & 1;                // N-half

    const float* base = qkv + (size_t)b*SEQ*900;
    const float scale = 0.1414213562373095f;  // 1/sqrt(50)

    if (tid < SEQ) mk[tid] = mask[b*SEQ + tid];
    int padcnt = __syncthreads_count(tid < SEQ && mask[b*SEQ + tid]);
    bool allpad = (padcnt == SEQ);

    // fill K^T: Kt[d][kk] = K[kk][d] (zero-padded), tf32-rounded
    for (int i = tid; i < 216*64; i += 256) {
        int kk = i >> 6, d = i & 63;
        float v = (kk < SEQ && d < DHEAD) ? base[(size_t)kk*900 + 300 + h*DHEAD + d] : 0.0f;
        Kt[d*KT_STRIDE + kk] = to_tf32(v);
    }
    // fill V: Vs[k][d] (zero-padded)
    for (int i = tid; i < VS_ELEMS; i += 256) {
        int k = i / VS_STRIDE, d = i % VS_STRIDE;
        float v = (k < SEQ && d < DHEAD) ? base[(size_t)k*900 + 600 + h*DHEAD + d] : 0.0f;
        Vs[i] = to_tf32(v);
    }
    __syncthreads();

    for (int qbase = 0; qbase < SEQ; qbase += 64) {
        // fill Q chunk (scaled, zero-padded)
        for (int i = tid; i < QS_ELEMS; i += 256) {
            int r = i / QS_STRIDE, d = i % QS_STRIDE;
            int q = qbase + r;
            float v = (q < SEQ && d < DHEAD) ? base[(size_t)q*900 + h*DHEAD + d]*scale : 0.0f;
            Qs[i] = to_tf32(v);
        }
        __syncthreads();

        // S = Q @ K^T : M=64 (4 warps x 16), N=208 (2 halves x 104), K=64
        {
            float sacc[13][4];
            #pragma unroll
            for (int nt = 0; nt < 13; nt++)
                #pragma unroll
                for (int r = 0; r < 4; r++) sacc[nt][r] = 0.0f;
            #pragma unroll
            for (int ks = 0; ks < 8; ks++) {
                int kb = ks*8;
                uint32_t a0 = __float_as_uint(Qs[(wm + g    )*QS_STRIDE + kb + tig    ]);
                uint32_t a1 = __float_as_uint(Qs[(wm + g + 8)*QS_STRIDE + kb + tig    ]);
                uint32_t a2 = __float_as_uint(Qs[(wm + g    )*QS_STRIDE + kb + tig + 4]);
                uint32_t a3 = __float_as_uint(Qs[(wm + g + 8)*QS_STRIDE + kb + tig + 4]);
                #pragma unroll
                for (int nt = 0; nt < 13; nt++) {
                    int cn = wn*104 + nt*8;
                    uint32_t b0 = __float_as_uint(Kt[(kb + tig    )*KT_STRIDE + cn + g]);
                    uint32_t b1 = __float_as_uint(Kt[(kb + tig + 4)*KT_STRIDE + cn + g]);
                    MMA_TF32(sacc[nt], a0, a1, a2, a3, b0, b1);
                }
            }
            #pragma unroll
            for (int nt = 0; nt < 13; nt++) {
                int col = wn*104 + nt*8 + tig*2;
                *(float2*)&Ps[(wm + g    )*PS_STRIDE + col] = make_float2(sacc[nt][0], sacc[nt][1]);
                *(float2*)&Ps[(wm + g + 8)*PS_STRIDE + col] = make_float2(sacc[nt][2], sacc[nt][3]);
            }
        }
        __syncthreads();

        // softmax over 200 cols; 4 threads per row
        {
            int row = tid >> 2, j = tid & 3;
            float m = -INFINITY;
            for (int k = j; k < SEQ; k += 4)
                if (!mk[k]) m = fmaxf(m, Ps[row*PS_STRIDE + k]);
            m = fmaxf(m, __shfl_xor_sync(0xffffffffu, m, 1));
            m = fmaxf(m, __shfl_xor_sync(0xffffffffu, m, 2));
            float ssum = 0.0f;
            for (int k = j; k < 208; k += 4) {
                float p = 0.0f;
                if (k < SEQ && !mk[k]) {
                    p = __expf(Ps[row*PS_STRIDE + k] - m);
                    ssum += p;
                }
                Ps[row*PS_STRIDE + k] = to_tf32(p);
            }
            ssum += __shfl_xor_sync(0xffffffffu, ssum, 1);
            ssum += __shfl_xor_sync(0xffffffffu, ssum, 2);
            if (j == 0) inv[row] = (allpad || ssum == 0.0f) ? 0.0f : 1.0f/ssum;
        }
        __syncthreads();

        // O = P @ V : M=64, N=64 (2 halves x 32), K=208
        {
            float oacc[4][4];
            #pragma unroll
            for (int nt = 0; nt < 4; nt++)
                #pragma unroll
                for (int r = 0; r < 4; r++) oacc[nt][r] = 0.0f;
            #pragma unroll
            for (int ks = 0; ks < 26; ks++) {
                int kb = ks*8;
                uint32_t a0 = __float_as_uint(Ps[(wm + g    )*PS_STRIDE + kb + tig    ]);
                uint32_t a1 = __float_as_uint(Ps[(wm + g + 8)*PS_STRIDE + kb + tig    ]);
                uint32_t a2 = __float_as_uint(Ps[(wm + g    )*PS_STRIDE + kb + tig + 4]);
                uint32_t a3 = __float_as_uint(Ps[(wm + g + 8)*PS_STRIDE + kb + tig + 4]);
                #pragma unroll
                for (int nt = 0; nt < 4; nt++) {
                    int cn = wn*32 + nt*8;
                    uint32_t b0 = __float_as_uint(Vs[(kb + tig    )*VS_STRIDE + cn + g]);
                    uint32_t b1 = __float_as_uint(Vs[(kb + tig + 4)*VS_STRIDE + cn + g]);
                    MMA_TF32(oacc[nt], a0, a1, a2, a3, b0, b1);
                }
            }
            float v0 = inv[wm + g], v1 = inv[wm + g + 8];
            int q0 = qbase + wm + g;
            #pragma unroll
            for (int nt = 0; nt < 4; nt++) {
                int col = wn*32 + nt*8 + tig*2;
                if (col < DHEAD) {
                    if (q0 < SEQ)
                        *(float2*)&out[(size_t)(b*SEQ + q0)*LDH + h*DHEAD + col] =
                            make_float2(oacc[nt][0]*v0, oacc[nt][1]*v0);
                    if (q0 + 8 < SEQ)
                        *(float2*)&out[(size_t)(b*SEQ + q0 + 8)*LDH + h*DHEAD + col] =
                            make_float2(oacc[nt][2]*v1, oacc[nt][3]*v1);
                }
            }
        }
        __syncthreads();
    }
}

// ---------------- fused residual add + LayerNorm ------------------------------
__global__ void ln_kernel(const float* __restrict__ X,
                          const float* __restrict__ Y,
                          const float* __restrict__ s,
                          const float* __restrict__ bcoef,
                          float* __restrict__ out,
                          unsigned char* maskout) {
    __shared__ float red[4];
    int r = blockIdx.x, tid = threadIdx.x;   // 128 threads
    float v[3]; int nd = 0;
    float local = 0.0f;
    for (int d = tid; d < DIM; d += 128) {
        float t = X[(size_t)r*LDH + d] + Y[(size_t)r*LDH + d];
        v[nd++] = t;
        local += t;
    }
    #pragma unroll
    for (int off = 16; off > 0; off >>= 1) local += __shfl_xor_sync(0xffffffffu, local, off);
    if ((tid & 31) == 0) red[tid >> 5] = local;
    __syncthreads();
    float mean = (red[0] + red[1] + red[2] + red[3]) / (float)DIM;
    __syncthreads();

    local = 0.0f;
    for (int i = 0; i < nd; i++) { float d0 = v[i] - mean; local += d0*d0; }
    #pragma unroll
    for (int off = 16; off > 0; off >>= 1) local += __shfl_xor_sync(0xffffffffu, local, off);
    if ((tid & 31) == 0) red[tid >> 5] = local;
    __syncthreads();
    float var = (red[0] + red[1] + red[2] + red[3]) / (float)DIM;
    float rstd = 1.0f / sqrtf(var + 1e-5f);

    bool allz = true;
    int nd2 = 0;
    for (int d = tid; d < DIM; d += 128) {
        float o = (v[nd2++] - mean)*rstd*s[d] + bcoef[d];
        out[(size_t)r*LDH + d] = o;
        if (o != 0.0f) allz = false;
    }
    if (maskout) {
        int cnt = __syncthreads_count(allz ? 1 : 0);
        if (tid == 0) maskout[r] = (cnt == 128) ? 1 : 0;
    }
}

// ---------------- head kernels ------------------------------------------------
__global__ void rowdot_kernel(const float* __restrict__ w1,
                              const float* __restrict__ b1) {
    int tid = threadIdx.x, warp = tid >> 5, lane = tid & 31;
    int r = blockIdx.x*8 + warp;
    if (r >= NROW) return;
    float acc = 0.0f;
    for (int d = lane; d < DIM; d += 32)
        acc += g_h[(size_t)r*LDH + d] * w1[d];
    #pragma unroll
    for (int off = 16; off > 0; off >>= 1) acc += __shfl_xor_sync(0xffffffffu, acc, off);
    if (lane == 0) g_s1[r] = acc + b1[0];
}

__global__ void head_kernel(const float* __restrict__ w2, const float* __restrict__ b2,
                            const float* __restrict__ wo, const float* __restrict__ bo,
                            const float* __restrict__ wa, const float* __restrict__ ba,
                            float* __restrict__ out) {
    __shared__ float s1s[SEQ];
    __shared__ float s2s[50];
    int b = blockIdx.x, tid = threadIdx.x;     // 64 threads
    for (int i = tid; i < SEQ; i += 64) s1s[i] = g_s1[b*SEQ + i];
    __syncthreads();
    if (tid < 50) {
        float acc = 0.0f;
        for (int s = 0; s < SEQ; s++) acc += s1s[s]*w2[s*50 + tid];
        s2s[tid] = gelu_f(acc + b2[tid]);
    }
    __syncthreads();
    if (tid < 7) {
        float acc = 0.0f;
        if (tid == 0) {
            for (int i = 0; i < 50; i++) acc += s2s[i]*wo[i];
            out[b*7] = acc + bo[0];
        } else {
            int j = tid - 1;
            for (int i = 0; i < 50; i++) acc += s2s[i]*wa[i*6 + j];
            out[b*7 + tid] = acc + ba[j];
        }
    }
}

// ---------------- launch ------------------------------------------------------
extern "C" void kernel_launch(void* const* d_in, const int* in_sizes, int n_in,
                              void* d_out, int out_size) {
    const int*   x_tok  = (const int*)  d_in[0];
    const float* emb    = (const float*)d_in[1];
    const float* qkv_w  = (const float*)d_in[2];
    const float* qkv_b  = (const float*)d_in[3];
    const float* out_w  = (const float*)d_in[4];
    const float* out_b  = (const float*)d_in[5];
    const float* ln1_s  = (const float*)d_in[6];
    const float* ln1_b  = (const float*)d_in[7];
    const float* ff1_w  = (const float*)d_in[8];
    const float* ff1_b  = (const float*)d_in[9];
    const float* ff2_w  = (const float*)d_in[10];
    const float* ff2_b  = (const float*)d_in[11];
    const float* ln2_s  = (const float*)d_in[12];
    const float* ln2_b  = (const float*)d_in[13];
    const float* lin1_w = (const float*)d_in[14];
    const float* lin1_b = (const float*)d_in[15];
    const float* lin2_w = (const float*)d_in[16];
    const float* lin2_b = (const float*)d_in[17];
    const float* lout_w = (const float*)d_in[18];
    const float* lout_b = (const float*)d_in[19];
    const float* laux_w = (const float*)d_in[20];
    const float* laux_b = (const float*)d_in[21];

    float *p_h, *p_h1, *p_qkv, *p_att, *p_prj, *p_ff1, *p_ff2;
    float *p_wqkv, *p_wprj, *p_wff1, *p_wff2;
    unsigned char *p_mask;
    cudaGetSymbolAddress((void**)&p_h,   g_h);
    cudaGetSymbolAddress((void**)&p_h1,  g_h1);
    cudaGetSymbolAddress((void**)&p_qkv, g_qkv);
    cudaGetSymbolAddress((void**)&p_att, g_att);
    cudaGetSymbolAddress((void**)&p_prj, g_prj);
    cudaGetSymbolAddress((void**)&p_ff1, g_ff1);
    cudaGetSymbolAddress((void**)&p_ff2, g_ff2);
    cudaGetSymbolAddress((void**)&p_mask, g_mask);
    cudaGetSymbolAddress((void**)&p_wqkv, g_pw_qkv);
    cudaGetSymbolAddress((void**)&p_wprj, g_pw_prj);
    cudaGetSymbolAddress((void**)&p_wff1, g_pw_ff1);
    cudaGetSymbolAddress((void**)&p_wff2, g_pw_ff2);

    cudaFuncSetAttribute(attn_kernel, cudaFuncAttributeMaxDynamicSharedMemorySize,
                         ATTN_SMEM);
    cudaFuncSetAttribute(mma_gemm_kernel, cudaFuncAttributeMaxDynamicSharedMemorySize,
                         GEMM_SMEM);

    sin_table_kernel<<<(SEQ*DIM + 255)/256, 256>>>();
    embed_kernel<<<(NROW*DIM + 255)/256, 256>>>(x_tok, emb);
    pack_all_kernel<<<(PK_S1+PK_S2+PK_S3+PK_S4+255)/256, 256>>>(qkv_w, out_w, ff1_w, ff2_w);

    for (int l = 0; l < 5; l++) {
        mma_gemm_kernel<<<dim3(8, NROW/BM), 256, GEMM_SMEM>>>(p_h, p_wqkv + (size_t)l*320*1024,
            qkv_b + l*900, p_qkv, 900, 320, LDH, 1024, 900, 0);
        attn_kernel<<<BATCH*NHEAD, 256, ATTN_SMEM>>>(p_qkv, p_mask, p_att);
        mma_gemm_kernel<<<dim3(3, NROW/BM), 256, GEMM_SMEM>>>(p_att, p_wprj + (size_t)l*320*384,
            out_b + l*DIM, p_prj, 300, 320, LDH, 384, LDH, 0);
        ln_kernel<<<NROW, 128>>>(p_h, p_prj, ln1_s + l*DIM, ln1_b + l*DIM, p_h1, nullptr);
        mma_gemm_kernel<<<dim3(5, NROW/BM), 256, GEMM_SMEM>>>(p_h1, p_wff1 + (size_t)l*320*640,
            ff1_b + l*2*DIM, p_ff1, 600, 320, LDH, 640, LDF, 1);
        mma_gemm_kernel<<<dim3(3, NROW/BM), 256, GEMM_SMEM>>>(p_ff1, p_wff2 + (size_t)l*608*384,
            ff2_b + l*DIM, p_ff2, 300, 608, LDF, 384, LDH, 0);
        ln_kernel<<<NROW, 128>>>(p_h1, p_ff2, ln2_s + l*DIM, ln2_b + l*DIM, p_h, p_mask);
    }

    rowdot_kernel<<<NROW/8, 256>>>(lin1_w, lin1_b);
    head_kernel<<<BATCH, 64>>>(lin2_w, lin2_b, lout_w, lout_b, laux_w, laux_b,
                               (float*)d_out);
}

// round 9
// speedup vs baseline: 3.1129x; 1.0005x over previous
#include <cuda_runtime.h>
#include <math.h>
#include <stdint.h>

// Problem constants
#define BATCH 256
#define SEQ   200
#define DIM   300
#define NHEAD 6
#define DHEAD 50
#define NROW  (BATCH*SEQ)        // 51200
#define LDH   320                // padded stride for D=300 activations
#define LDF   608                // padded stride for 600-dim FF hidden
#define GELU_C 0.7978845608028654f

// ---------------- scratch (device globals; zero-initialized) ------------------
__device__ float g_sin[SEQ*DIM];
__device__ float g_h  [NROW*LDH];
__device__ float g_h1 [NROW*LDH];
__device__ float g_qkv[NROW*900];
__device__ float g_att[NROW*LDH];
__device__ float g_prj[NROW*LDH];
__device__ float g_ff1[NROW*LDF];
__device__ float g_ff2[NROW*LDH];
__device__ float g_s1 [NROW];
__device__ unsigned char g_mask[NROW];

// packed tf32 weights, all 5 layers, zero padded to Kp x Np
__device__ float g_pw_qkv[5*320*1024];
__device__ float g_pw_prj[5*320*384];
__device__ float g_pw_ff1[5*320*640];
__device__ float g_pw_ff2[5*608*384];

__device__ __forceinline__ float gelu_f(float x) {
    float x3 = x*x*x;
    return 0.5f*x*(1.0f + tanhf(GELU_C*(x + 0.044715f*x3)));
}
__device__ __forceinline__ float to_tf32(float v) {
    uint32_t t;
    asm("cvt.rna.tf32.f32 %0, %1;" : "=r"(t) : "f"(v));
    return __uint_as_float(t);
}
__device__ __forceinline__ uint32_t smemu32(const void* p) {
    return (uint32_t)__cvta_generic_to_shared(p);
}
#define CP16(dst, src) asm volatile("cp.async.cg.shared.global [%0], [%1], 16;\n" :: "r"(dst), "l"(src))
#define CP_COMMIT()    asm volatile("cp.async.commit_group;\n" ::)
#define CP_WAIT(N)     asm volatile("cp.async.wait_group %0;\n" :: "n"(N))

#define MMA_TF32(acc, a0,a1,a2,a3, b0,b1) \
    asm volatile( \
        "mma.sync.aligned.m16n8k8.row.col.f32.tf32.tf32.f32 " \
        "{%0,%1,%2,%3}, {%4,%5,%6,%7}, {%8,%9}, {%0,%1,%2,%3};" \
        : "+f"((acc)[0]), "+f"((acc)[1]), "+f"((acc)[2]), "+f"((acc)[3]) \
        : "r"(a0), "r"(a1), "r"(a2), "r"(a3), "r"(b0), "r"(b1))

// ---------------- sinusoid table ----------------------------------------------
__global__ void sin_table_kernel() {
    int idx = blockIdx.x*blockDim.x + threadIdx.x;
    if (idx >= SEQ*DIM) return;
    int pos = idx / DIM, i = idx % DIM;
    double ang = (double)pos / pow(10000.0, 2.0*(double)(i/2)/(double)DIM);
    g_sin[idx] = (float)((i & 1) ? cos(ang) : sin(ang));
}

// ---------------- embedding + pos-enc + initial mask --------------------------
__global__ void embed_kernel(const int* __restrict__ tok,
                             const float* __restrict__ emb) {
    int idx = blockIdx.x*blockDim.x + threadIdx.x;
    if (idx >= NROW*DIM) return;
    int r = idx / DIM, d = idx % DIM;
    int t = tok[r];
    float v = emb[(size_t)t*DIM + d];
    if (t != 0) v += g_sin[(r % SEQ)*DIM + d];
    g_h[(size_t)r*LDH + d] = v;
    if (d == 0) g_mask[r] = (t == 0) ? 1 : 0;
}

// ---------------- merged weight packing (all 4 weights, all 5 layers) ---------
#define PK_S1 (5*320*1024)
#define PK_S2 (5*320*384)
#define PK_S3 (5*320*640)
#define PK_S4 (5*608*384)
__device__ __forceinline__ void pack_one(const float* __restrict__ src,
                                         float* __restrict__ dst, int i,
                                         int K, int N, int Kp, int Np) {
    int per = Kp*Np;
    int l = i / per, r = i % per;
    int k = r / Np, n = r % Np;
    float v = (k < K && n < N) ? src[(size_t)l*K*N + (size_t)k*N + n] : 0.0f;
    dst[i] = to_tf32(v);
}
__global__ void pack_all_kernel(const float* __restrict__ qkv_w,
                                const float* __restrict__ out_w,
                                const float* __restrict__ ff1_w,
                                const float* __restrict__ ff2_w) {
    int i = blockIdx.x*blockDim.x + threadIdx.x;
    if (i < PK_S1) { pack_one(qkv_w, g_pw_qkv, i, 300, 900, 320, 1024); return; }
    i -= PK_S1;
    if (i < PK_S2) { pack_one(out_w, g_pw_prj, i, 300, 300, 320, 384); return; }
    i -= PK_S2;
    if (i < PK_S3) { pack_one(ff1_w, g_pw_ff1, i, 300, 600, 320, 640); return; }
    i -= PK_S3;
    if (i < PK_S4) { pack_one(ff2_w, g_pw_ff2, i, 600, 300, 608, 384); return; }
}

// ---------------- TF32 tensor-core GEMM (4-stage pipeline) --------------------
#define BM 128
#define BN 128
#define BK 16
#define STAGES 4
#define ASTRIDE 20
#define BSTRIDE 136
#define A_ELEMS (BM*ASTRIDE)
#define B_ELEMS (BK*BSTRIDE)
#define GEMM_SMEM ((STAGES*(A_ELEMS + B_ELEMS))*4)   // 75776 bytes

__global__ __launch_bounds__(256, 2) void mma_gemm_kernel(
        const float* __restrict__ A, const float* __restrict__ Bp,
        const float* __restrict__ bias, float* __restrict__ C,
        int N, int Kp, int lda, int Np, int ldc, int act) {
    extern __shared__ float dsm[];
    float* Asm = dsm;
    float* Bsm = dsm + STAGES*A_ELEMS;

    int tid = threadIdx.x;
    int warp = tid >> 5, lane = tid & 31;
    int g = lane >> 2, tig = lane & 3;
    int mw = (warp >> 2)*64, nw = (warp & 3)*32;
    int bm = blockIdx.y*BM, bn = blockIdx.x*BN;

    const float* Abase = A + (size_t)bm*lda;
    const float* Bbase = Bp + bn;

    float acc[4][4][4];
    #pragma unroll
    for (int i = 0; i < 4; i++)
        #pragma unroll
        for (int j = 0; j < 4; j++)
            #pragma unroll
            for (int r = 0; r < 4; r++) acc[i][j][r] = 0.0f;

    int nIter = Kp / BK;

    int am0 = tid >> 2,            ac0 = (tid & 3)*4;
    int am1 = (tid + 256) >> 2,    ac1 = ac0;
    int bk0 = tid >> 5,            bc0 = (tid & 31)*4;
    int bk1 = (tid + 256) >> 5,    bc1 = bc0;

    auto loadStage = [&](int it, int s) {
        int k0 = it*BK;
        float* As = Asm + s*A_ELEMS;
        float* Bs = Bsm + s*B_ELEMS;
        CP16(smemu32(&As[am0*ASTRIDE + ac0]), Abase + (size_t)am0*lda + k0 + ac0);
        CP16(smemu32(&As[am1*ASTRIDE + ac1]), Abase + (size_t)am1*lda + k0 + ac1);
        CP16(smemu32(&Bs[bk0*BSTRIDE + bc0]), Bbase + (size_t)(k0+bk0)*Np + bc0);
        CP16(smemu32(&Bs[bk1*BSTRIDE + bc1]), Bbase + (size_t)(k0+bk1)*Np + bc1);
    };

    #pragma unroll
    for (int s = 0; s < STAGES-1; s++) {
        loadStage(s, s);
        CP_COMMIT();
    }

    for (int it = 0; it < nIter; it++) {
        int cur = it & (STAGES-1);
        __syncthreads();
        if (it + STAGES-1 < nIter)
            loadStage(it + STAGES-1, (it + STAGES-1) & (STAGES-1));
        CP_COMMIT();
        CP_WAIT(STAGES-1);
        __syncthreads();

        const float* As = Asm + cur*A_ELEMS;
        const float* Bs = Bsm + cur*B_ELEMS;
        #pragma unroll
        for (int ks = 0; ks < 2; ks++) {
            int kb = ks*8;
            uint32_t af[4][4], bf[4][2];
            #pragma unroll
            for (int mt = 0; mt < 4; mt++) {
                int rm = mw + mt*16;
                af[mt][0] = __float_as_uint(As[(rm + g    )*ASTRIDE + kb + tig    ]);
                af[mt][1] = __float_as_uint(As[(rm + g + 8)*ASTRIDE + kb + tig    ]);
                af[mt][2] = __float_as_uint(As[(rm + g    )*ASTRIDE + kb + tig + 4]);
                af[mt][3] = __float_as_uint(As[(rm + g + 8)*ASTRIDE + kb + tig + 4]);
            }
            #pragma unroll
            for (int nt = 0; nt < 4; nt++) {
                int cn = nw + nt*8;
                bf[nt][0] = __float_as_uint(Bs[(kb + tig    )*BSTRIDE + cn + g]);
                bf[nt][1] = __float_as_uint(Bs[(kb + tig + 4)*BSTRIDE + cn + g]);
            }
            #pragma unroll
            for (int mt = 0; mt < 4; mt++)
                #pragma unroll
                for (int nt = 0; nt < 4; nt++)
                    MMA_TF32(acc[mt][nt], af[mt][0], af[mt][1], af[mt][2], af[mt][3],
                             bf[nt][0], bf[nt][1]);
        }
    }

    #pragma unroll
    for (int mt = 0; mt < 4; mt++) {
        int row0 = bm + mw + mt*16 + g;
        #pragma unroll
        for (int nt = 0; nt < 4; nt++) {
            int col = bn + nw + nt*8 + tig*2;
            if (col < N) {
                float b0 = bias[col], b1 = bias[col+1];
                float v0 = acc[mt][nt][0] + b0;
                float v1 = acc[mt][nt][1] + b1;
                float v2 = acc[mt][nt][2] + b0;
                float v3 = acc[mt][nt][3] + b1;
                if (act == 1) { v0 = gelu_f(v0); v1 = gelu_f(v1); v2 = gelu_f(v2); v3 = gelu_f(v3); }
                *(float2*)&C[(size_t)row0*ldc + col]     = make_float2(v0, v1);
                *(float2*)&C[(size_t)(row0+8)*ldc + col] = make_float2(v2, v3);
            }
        }
    }
}

// ---------------- tensor-core attention v2 ------------------------------------
// One block per (qchunk, b*h). K/V streamed through a shared 64-wide tile
// buffer -> 90.6 KB smem -> 2 blocks/SM. Same m16n8k8 fragment patterns.
#define AQ_STRIDE 68      // Qs[64][68]
#define AP_STRIDE 212     // Ps[64][212] (cols 0..207)
#define AT_STRIDE 72      // Tb[64][72]  (K^T tile: [d][k]; V tile: [k][d])
#define AQ_ELEMS (64*AQ_STRIDE)
#define AP_ELEMS (64*AP_STRIDE)
#define AT_ELEMS (64*AT_STRIDE)
#define ATTN_SMEM ((AQ_ELEMS + AP_ELEMS + AT_ELEMS + 64)*4 + 256)

__global__ __launch_bounds__(256, 2) void attn_kernel(
        const float* __restrict__ qkv,
        const unsigned char* __restrict__ mask,
        float* __restrict__ out) {
    extern __shared__ float sm[];
    float* Qs  = sm;
    float* Ps  = Qs + AQ_ELEMS;
    float* Tb  = Ps + AP_ELEMS;
    float* inv = Tb + AT_ELEMS;
    unsigned char* mk = (unsigned char*)(inv + 64);

    int bh = blockIdx.y;
    int b = bh / NHEAD, h = bh % NHEAD;
    int qbase = blockIdx.x * 64;
    int tid = threadIdx.x;
    int warp = tid >> 5, lane = tid & 31;
    int g = lane >> 2, tig = lane & 3;
    int wm = (warp >> 1)*16;          // 4 m-positions
    int wn = warp & 1;                // 2 n-halves

    const float* base = qkv + (size_t)b*SEQ*900;
    const float scale = 0.1414213562373095f;  // 1/sqrt(50)

    if (tid < SEQ) mk[tid] = mask[b*SEQ + tid];
    int padcnt = __syncthreads_count(tid < SEQ && mask[b*SEQ + tid]);
    bool allpad = (padcnt == SEQ);

    // fill Q chunk (scaled, tf32, zero-padded)
    for (int i = tid; i < AQ_ELEMS; i += 256) {
        int r = i / AQ_STRIDE, d = i % AQ_STRIDE;
        int q = qbase + r;
        float v = (q < SEQ && d < DHEAD) ? base[(size_t)q*900 + h*DHEAD + d]*scale : 0.0f;
        Qs[i] = to_tf32(v);
    }
    __syncthreads();

    // ---- S = Q @ K^T, k streamed in 4 tiles of 64 ----
    for (int kt = 0; kt < 4; kt++) {
        int K0 = kt*64;
        // fill K^T tile: Tb[d][klocal] = K[K0+klocal][d]
        for (int i = tid; i < 4096; i += 256) {
            int k = i >> 6, d = i & 63;
            float v = (K0 + k < SEQ && d < DHEAD)
                    ? base[(size_t)(K0+k)*900 + 300 + h*DHEAD + d] : 0.0f;
            Tb[d*AT_STRIDE + k] = to_tf32(v);
        }
        __syncthreads();

        float sacc[4][4];
        #pragma unroll
        for (int nt = 0; nt < 4; nt++)
            #pragma unroll
            for (int r = 0; r < 4; r++) sacc[nt][r] = 0.0f;
        #pragma unroll
        for (int ks = 0; ks < 8; ks++) {
            int kb = ks*8;
            uint32_t a0 = __float_as_uint(Qs[(wm + g    )*AQ_STRIDE + kb + tig    ]);
            uint32_t a1 = __float_as_uint(Qs[(wm + g + 8)*AQ_STRIDE + kb + tig    ]);
            uint32_t a2 = __float_as_uint(Qs[(wm + g    )*AQ_STRIDE + kb + tig + 4]);
            uint32_t a3 = __float_as_uint(Qs[(wm + g + 8)*AQ_STRIDE + kb + tig + 4]);
            #pragma unroll
            for (int nt = 0; nt < 4; nt++) {
                int cn = wn*32 + nt*8;
                uint32_t b0 = __float_as_uint(Tb[(kb + tig    )*AT_STRIDE + cn + g]);
                uint32_t b1 = __float_as_uint(Tb[(kb + tig + 4)*AT_STRIDE + cn + g]);
                MMA_TF32(sacc[nt], a0, a1, a2, a3, b0, b1);
            }
        }
        #pragma unroll
        for (int nt = 0; nt < 4; nt++) {
            int col = K0 + wn*32 + nt*8 + tig*2;
            if (col < 208) {
                *(float2*)&Ps[(wm + g    )*AP_STRIDE + col] = make_float2(sacc[nt][0], sacc[nt][1]);
                *(float2*)&Ps[(wm + g + 8)*AP_STRIDE + col] = make_float2(sacc[nt][2], sacc[nt][3]);
            }
        }
        __syncthreads();
    }

    // ---- softmax over 200 cols; 4 threads per row ----
    {
        int row = tid >> 2, j = tid & 3;
        float m = -INFINITY;
        for (int k = j; k < SEQ; k += 4)
            if (!mk[k]) m = fmaxf(m, Ps[row*AP_STRIDE + k]);
        m = fmaxf(m, __shfl_xor_sync(0xffffffffu, m, 1));
        m = fmaxf(m, __shfl_xor_sync(0xffffffffu, m, 2));
        float ssum = 0.0f;
        for (int k = j; k < 208; k += 4) {
            float p = 0.0f;
            if (k < SEQ && !mk[k]) {
                p = __expf(Ps[row*AP_STRIDE + k] - m);
                ssum += p;
            }
            Ps[row*AP_STRIDE + k] = to_tf32(p);
        }
        ssum += __shfl_xor_sync(0xffffffffu, ssum, 1);
        ssum += __shfl_xor_sync(0xffffffffu, ssum, 2);
        if (j == 0) inv[row] = (allpad || ssum == 0.0f) ? 0.0f : 1.0f/ssum;
    }
    __syncthreads();

    // ---- O = P @ V, k streamed in tiles (8,8,8,2 k-steps) ----
    float oacc[4][4];
    #pragma unroll
    for (int nt = 0; nt < 4; nt++)
        #pragma unroll
        for (int r = 0; r < 4; r++) oacc[nt][r] = 0.0f;

    for (int kt = 0; kt < 4; kt++) {
        int K0 = kt*64;
        int nk = (kt == 3) ? 2 : 8;
        // fill V tile: Tb[klocal][d] = V[K0+klocal][d]
        for (int i = tid; i < 4096; i += 256) {
            int k = i >> 6, d = i & 63;
            float v = (K0 + k < SEQ && d < DHEAD)
                    ? base[(size_t)(K0+k)*900 + 600 + h*DHEAD + d] : 0.0f;
            Tb[k*AT_STRIDE + d] = to_tf32(v);
        }
        __syncthreads();

        for (int ks = 0; ks < nk; ks++) {
            int kb = ks*8;
            uint32_t a0 = __float_as_uint(Ps[(wm + g    )*AP_STRIDE + K0 + kb + tig    ]);
            uint32_t a1 = __float_as_uint(Ps[(wm + g + 8)*AP_STRIDE + K0 + kb + tig    ]);
            uint32_t a2 = __float_as_uint(Ps[(wm + g    )*AP_STRIDE + K0 + kb + tig + 4]);
            uint32_t a3 = __float_as_uint(Ps[(wm + g + 8)*AP_STRIDE + K0 + kb + tig + 4]);
            #pragma unroll
            for (int nt = 0; nt < 4; nt++) {
                int cn = wn*32 + nt*8;
                uint32_t b0 = __float_as_uint(Tb[(kb + tig    )*AT_STRIDE + cn + g]);
                uint32_t b1 = __float_as_uint(Tb[(kb + tig + 4)*AT_STRIDE + cn + g]);
                MMA_TF32(oacc[nt], a0, a1, a2, a3, b0, b1);
            }
        }
        __syncthreads();
    }

    // ---- epilogue: normalize + store ----
    {
        float v0 = inv[wm + g], v1 = inv[wm + g + 8];
        int q0 = qbase + wm + g;
        #pragma unroll
        for (int nt = 0; nt < 4; nt++) {
            int col = wn*32 + nt*8 + tig*2;
            if (col < DHEAD) {
                if (q0 < SEQ)
                    *(float2*)&out[(size_t)(b*SEQ + q0)*LDH + h*DHEAD + col] =
                        make_float2(oacc[nt][0]*v0, oacc[nt][1]*v0);
                if (q0 + 8 < SEQ)
                    *(float2*)&out[(size_t)(b*SEQ + q0 + 8)*LDH + h*DHEAD + col] =
                        make_float2(oacc[nt][2]*v1, oacc[nt][3]*v1);
            }
        }
    }
}

// ---------------- fused residual add + LayerNorm ------------------------------
__global__ void ln_kernel(const float* __restrict__ X,
                          const float* __restrict__ Y,
                          const float* __restrict__ s,
                          const float* __restrict__ bcoef,
                          float* __restrict__ out,
                          unsigned char* maskout) {
    __shared__ float red[4];
    int r = blockIdx.x, tid = threadIdx.x;   // 128 threads
    float v[3]; int nd = 0;
    float local = 0.0f;
    for (int d = tid; d < DIM; d += 128) {
        float t = X[(size_t)r*LDH + d] + Y[(size_t)r*LDH + d];
        v[nd++] = t;
        local += t;
    }
    #pragma unroll
    for (int off = 16; off > 0; off >>= 1) local += __shfl_xor_sync(0xffffffffu, local, off);
    if ((tid & 31) == 0) red[tid >> 5] = local;
    __syncthreads();
    float mean = (red[0] + red[1] + red[2] + red[3]) / (float)DIM;
    __syncthreads();

    local = 0.0f;
    for (int i = 0; i < nd; i++) { float d0 = v[i] - mean; local += d0*d0; }
    #pragma unroll
    for (int off = 16; off > 0; off >>= 1) local += __shfl_xor_sync(0xffffffffu, local, off);
    if ((tid & 31) == 0) red[tid >> 5] = local;
    __syncthreads();
    float var = (red[0] + red[1] + red[2] + red[3]) / (float)DIM;
    float rstd = 1.0f / sqrtf(var + 1e-5f);

    bool allz = true;
    int nd2 = 0;
    for (int d = tid; d < DIM; d += 128) {
        float o = (v[nd2++] - mean)*rstd*s[d] + bcoef[d];
        out[(size_t)r*LDH + d] = o;
        if (o != 0.0f) allz = false;
    }
    if (maskout) {
        int cnt = __syncthreads_count(allz ? 1 : 0);
        if (tid == 0) maskout[r] = (cnt == 128) ? 1 : 0;
    }
}

// ---------------- head kernels ------------------------------------------------
__global__ void rowdot_kernel(const float* __restrict__ w1,
                              const float* __restrict__ b1) {
    int tid = threadIdx.x, warp = tid >> 5, lane = tid & 31;
    int r = blockIdx.x*8 + warp;
    if (r >= NROW) return;
    float acc = 0.0f;
    for (int d = lane; d < DIM; d += 32)
        acc += g_h[(size_t)r*LDH + d] * w1[d];
    #pragma unroll
    for (int off = 16; off > 0; off >>= 1) acc += __shfl_xor_sync(0xffffffffu, acc, off);
    if (lane == 0) g_s1[r] = acc + b1[0];
}

__global__ void head_kernel(const float* __restrict__ w2, const float* __restrict__ b2,
                            const float* __restrict__ wo, const float* __restrict__ bo,
                            const float* __restrict__ wa, const float* __restrict__ ba,
                            float* __restrict__ out) {
    __shared__ float s1s[SEQ];
    __shared__ float s2s[50];
    int b = blockIdx.x, tid = threadIdx.x;     // 64 threads
    for (int i = tid; i < SEQ; i += 64) s1s[i] = g_s1[b*SEQ + i];
    __syncthreads();
    if (tid < 50) {
        float acc = 0.0f;
        for (int s = 0; s < SEQ; s++) acc += s1s[s]*w2[s*50 + tid];
        s2s[tid] = gelu_f(acc + b2[tid]);
    }
    __syncthreads();
    if (tid < 7) {
        float acc = 0.0f;
        if (tid == 0) {
            for (int i = 0; i < 50; i++) acc += s2s[i]*wo[i];
            out[b*7] = acc + bo[0];
        } else {
            int j = tid - 1;
            for (int i = 0; i < 50; i++) acc += s2s[i]*wa[i*6 + j];
            out[b*7 + tid] = acc + ba[j];
        }
    }
}

// ---------------- launch ------------------------------------------------------
extern "C" void kernel_launch(void* const* d_in, const int* in_sizes, int n_in,
                              void* d_out, int out_size) {
    const int*   x_tok  = (const int*)  d_in[0];
    const float* emb    = (const float*)d_in[1];
    const float* qkv_w  = (const float*)d_in[2];
    const float* qkv_b  = (const float*)d_in[3];
    const float* out_w  = (const float*)d_in[4];
    const float* out_b  = (const float*)d_in[5];
    const float* ln1_s  = (const float*)d_in[6];
    const float* ln1_b  = (const float*)d_in[7];
    const float* ff1_w  = (const float*)d_in[8];
    const float* ff1_b  = (const float*)d_in[9];
    const float* ff2_w  = (const float*)d_in[10];
    const float* ff2_b  = (const float*)d_in[11];
    const float* ln2_s  = (const float*)d_in[12];
    const float* ln2_b  = (const float*)d_in[13];
    const float* lin1_w = (const float*)d_in[14];
    const float* lin1_b = (const float*)d_in[15];
    const float* lin2_w = (const float*)d_in[16];
    const float* lin2_b = (const float*)d_in[17];
    const float* lout_w = (const float*)d_in[18];
    const float* lout_b = (const float*)d_in[19];
    const float* laux_w = (const float*)d_in[20];
    const float* laux_b = (const float*)d_in[21];

    float *p_h, *p_h1, *p_qkv, *p_att, *p_prj, *p_ff1, *p_ff2;
    float *p_wqkv, *p_wprj, *p_wff1, *p_wff2;
    unsigned char *p_mask;
    cudaGetSymbolAddress((void**)&p_h,   g_h);
    cudaGetSymbolAddress((void**)&p_h1,  g_h1);
    cudaGetSymbolAddress((void**)&p_qkv, g_qkv);
    cudaGetSymbolAddress((void**)&p_att, g_att);
    cudaGetSymbolAddress((void**)&p_prj, g_prj);
    cudaGetSymbolAddress((void**)&p_ff1, g_ff1);
    cudaGetSymbolAddress((void**)&p_ff2, g_ff2);
    cudaGetSymbolAddress((void**)&p_mask, g_mask);
    cudaGetSymbolAddress((void**)&p_wqkv, g_pw_qkv);
    cudaGetSymbolAddress((void**)&p_wprj, g_pw_prj);
    cudaGetSymbolAddress((void**)&p_wff1, g_pw_ff1);
    cudaGetSymbolAddress((void**)&p_wff2, g_pw_ff2);

    cudaFuncSetAttribute(attn_kernel, cudaFuncAttributeMaxDynamicSharedMemorySize,
                         ATTN_SMEM);
    cudaFuncSetAttribute(mma_gemm_kernel, cudaFuncAttributeMaxDynamicSharedMemorySize,
                         GEMM_SMEM);

    sin_table_kernel<<<(SEQ*DIM + 255)/256, 256>>>();
    embed_kernel<<<(NROW*DIM + 255)/256, 256>>>(x_tok, emb);
    pack_all_kernel<<<(PK_S1+PK_S2+PK_S3+PK_S4+255)/256, 256>>>(qkv_w, out_w, ff1_w, ff2_w);

    for (int l = 0; l < 5; l++) {
        mma_gemm_kernel<<<dim3(8, NROW/BM), 256, GEMM_SMEM>>>(p_h, p_wqkv + (size_t)l*320*1024,
            qkv_b + l*900, p_qkv, 900, 320, LDH, 1024, 900, 0);
        attn_kernel<<<dim3(4, BATCH*NHEAD), 256, ATTN_SMEM>>>(p_qkv, p_mask, p_att);
        mma_gemm_kernel<<<dim3(3, NROW/BM), 256, GEMM_SMEM>>>(p_att, p_wprj + (size_t)l*320*384,
            out_b + l*DIM, p_prj, 300, 320, LDH, 384, LDH, 0);
        ln_kernel<<<NROW, 128>>>(p_h, p_prj, ln1_s + l*DIM, ln1_b + l*DIM, p_h1, nullptr);
        mma_gemm_kernel<<<dim3(5, NROW/BM), 256, GEMM_SMEM>>>(p_h1, p_wff1 + (size_t)l*320*640,
            ff1_b + l*2*DIM, p_ff1, 600, 320, LDH, 640, LDF, 1);
        mma_gemm_kernel<<<dim3(3, NROW/BM), 256, GEMM_SMEM>>>(p_ff1, p_wff2 + (size_t)l*608*384,
            ff2_b + l*DIM, p_ff2, 300, 608, LDF, 384, LDH, 0);
        ln_kernel<<<NROW, 128>>>(p_h1, p_ff2, ln2_s + l*DIM, ln2_b + l*DIM, p_h, p_mask);
    }

    rowdot_kernel<<<NROW/8, 256>>>(lin1_w, lin1_b);
    head_kernel<<<BATCH, 64>>>(lin2_w, lin2_b, lout_w, lout_b, laux_w, laux_b,
                               (float*)d_out);
}

// round 10
// speedup vs baseline: 3.1833x; 1.0226x over previous
#include <cuda_runtime.h>
#include <math.h>
#include <stdint.h>

// Problem constants
#define BATCH 256
#define SEQ   200
#define DIM   300
#define NHEAD 6
#define DHEAD 50
#define NROW  (BATCH*SEQ)        // 51200
#define LDH   320                // padded stride for D=300 activations
#define LDF   608                // padded stride for 600-dim FF hidden
#define GELU_C 0.7978845608028654f

// ---------------- scratch (device globals; zero-initialized) ------------------
__device__ float g_sin[SEQ*DIM];
__device__ float g_h  [NROW*LDH];
__device__ float g_h1 [NROW*LDH];
__device__ float g_qkv[NROW*900];
__device__ float g_att[NROW*LDH];
__device__ float g_prj[NROW*LDH];
__device__ float g_ff1[NROW*LDF];
__device__ float g_ff2[NROW*LDH];
__device__ float g_s1 [NROW];
__device__ unsigned char g_mask[NROW];

// packed tf32 weights, all 5 layers, zero padded to Kp x Np
__device__ float g_pw_qkv[5*320*1024];
__device__ float g_pw_prj[5*320*384];
__device__ float g_pw_ff1[5*320*640];
__device__ float g_pw_ff2[5*608*384];

__device__ __forceinline__ float gelu_f(float x) {
    float x3 = x*x*x;
    return 0.5f*x*(1.0f + tanhf(GELU_C*(x + 0.044715f*x3)));
}
__device__ __forceinline__ float to_tf32(float v) {
    uint32_t t;
    asm("cvt.rna.tf32.f32 %0, %1;" : "=r"(t) : "f"(v));
    return __uint_as_float(t);
}
__device__ __forceinline__ uint32_t smemu32(const void* p) {
    return (uint32_t)__cvta_generic_to_shared(p);
}
#define CP16(dst, src) asm volatile("cp.async.cg.shared.global [%0], [%1], 16;\n" :: "r"(dst), "l"(src))
#define CP_COMMIT()    asm volatile("cp.async.commit_group;\n" ::)
#define CP_WAIT(N)     asm volatile("cp.async.wait_group %0;\n" :: "n"(N))

#define MMA_TF32(acc, a0,a1,a2,a3, b0,b1) \
    asm volatile( \
        "mma.sync.aligned.m16n8k8.row.col.f32.tf32.tf32.f32 " \
        "{%0,%1,%2,%3}, {%4,%5,%6,%7}, {%8,%9}, {%0,%1,%2,%3};" \
        : "+f"((acc)[0]), "+f"((acc)[1]), "+f"((acc)[2]), "+f"((acc)[3]) \
        : "r"(a0), "r"(a1), "r"(a2), "r"(a3), "r"(b0), "r"(b1))

// ---------------- sinusoid table ----------------------------------------------
__global__ void sin_table_kernel() {
    int idx = blockIdx.x*blockDim.x + threadIdx.x;
    if (idx >= SEQ*DIM) return;
    int pos = idx / DIM, i = idx % DIM;
    double ang = (double)pos / pow(10000.0, 2.0*(double)(i/2)/(double)DIM);
    g_sin[idx] = (float)((i & 1) ? cos(ang) : sin(ang));
}

// ---------------- embedding + pos-enc + initial mask --------------------------
__global__ void embed_kernel(const int* __restrict__ tok,
                             const float* __restrict__ emb) {
    int idx = blockIdx.x*blockDim.x + threadIdx.x;
    if (idx >= NROW*DIM) return;
    int r = idx / DIM, d = idx % DIM;
    int t = tok[r];
    float v = emb[(size_t)t*DIM + d];
    if (t != 0) v += g_sin[(r % SEQ)*DIM + d];
    g_h[(size_t)r*LDH + d] = v;
    if (d == 0) g_mask[r] = (t == 0) ? 1 : 0;
}

// ---------------- merged weight packing (all 4 weights, all 5 layers) ---------
#define PK_S1 (5*320*1024)
#define PK_S2 (5*320*384)
#define PK_S3 (5*320*640)
#define PK_S4 (5*608*384)
__device__ __forceinline__ void pack_one(const float* __restrict__ src,
                                         float* __restrict__ dst, int i,
                                         int K, int N, int Kp, int Np) {
    int per = Kp*Np;
    int l = i / per, r = i % per;
    int k = r / Np, n = r % Np;
    float v = (k < K && n < N) ? src[(size_t)l*K*N + (size_t)k*N + n] : 0.0f;
    dst[i] = to_tf32(v);
}
__global__ void pack_all_kernel(const float* __restrict__ qkv_w,
                                const float* __restrict__ out_w,
                                const float* __restrict__ ff1_w,
                                const float* __restrict__ ff2_w) {
    int i = blockIdx.x*blockDim.x + threadIdx.x;
    if (i < PK_S1) { pack_one(qkv_w, g_pw_qkv, i, 300, 900, 320, 1024); return; }
    i -= PK_S1;
    if (i < PK_S2) { pack_one(out_w, g_pw_prj, i, 300, 300, 320, 384); return; }
    i -= PK_S2;
    if (i < PK_S3) { pack_one(ff1_w, g_pw_ff1, i, 300, 600, 320, 640); return; }
    i -= PK_S3;
    if (i < PK_S4) { pack_one(ff2_w, g_pw_ff2, i, 600, 300, 608, 384); return; }
}

// ---------------- TF32 tensor-core GEMM (5-stage, single-sync mainloop) -------
#define BM 128
#define BN 128
#define BK 16
#define STAGES 5
#define ASTRIDE 20
#define BSTRIDE 136
#define A_ELEMS (BM*ASTRIDE)
#define B_ELEMS (BK*BSTRIDE)
#define GEMM_SMEM ((STAGES*(A_ELEMS + B_ELEMS))*4)   // 94720 bytes

__global__ __launch_bounds__(256, 2) void mma_gemm_kernel(
        const float* __restrict__ A, const float* __restrict__ Bp,
        const float* __restrict__ bias, float* __restrict__ C,
        int N, int Kp, int lda, int Np, int ldc, int act) {
    extern __shared__ float dsm[];
    float* Asm = dsm;
    float* Bsm = dsm + STAGES*A_ELEMS;

    int tid = threadIdx.x;
    int warp = tid >> 5, lane = tid & 31;
    int g = lane >> 2, tig = lane & 3;
    int mw = (warp >> 2)*64, nw = (warp & 3)*32;
    int bm = blockIdx.y*BM, bn = blockIdx.x*BN;

    const float* Abase = A + (size_t)bm*lda;
    const float* Bbase = Bp + bn;

    float acc[4][4][4];
    #pragma unroll
    for (int i = 0; i < 4; i++)
        #pragma unroll
        for (int j = 0; j < 4; j++)
            #pragma unroll
            for (int r = 0; r < 4; r++) acc[i][j][r] = 0.0f;

    int nIter = Kp / BK;

    int am0 = tid >> 2,            ac0 = (tid & 3)*4;
    int am1 = (tid + 256) >> 2,    ac1 = ac0;
    int bk0 = tid >> 5,            bc0 = (tid & 31)*4;
    int bk1 = (tid + 256) >> 5,    bc1 = bc0;

    auto loadStage = [&](int it, int s) {
        int k0 = it*BK;
        float* As = Asm + s*A_ELEMS;
        float* Bs = Bsm + s*B_ELEMS;
        CP16(smemu32(&As[am0*ASTRIDE + ac0]), Abase + (size_t)am0*lda + k0 + ac0);
        CP16(smemu32(&As[am1*ASTRIDE + ac1]), Abase + (size_t)am1*lda + k0 + ac1);
        CP16(smemu32(&Bs[bk0*BSTRIDE + bc0]), Bbase + (size_t)(k0+bk0)*Np + bc0);
        CP16(smemu32(&Bs[bk1*BSTRIDE + bc1]), Bbase + (size_t)(k0+bk1)*Np + bc1);
    };

    // prologue: fill STAGES-1 stages
    #pragma unroll
    for (int s = 0; s < STAGES-1; s++) {
        loadStage(s, s);
        CP_COMMIT();
    }

    int cur = 0;
    for (int it = 0; it < nIter; it++) {
        CP_WAIT(STAGES-2);        // stage `it` group fully landed (own thread)
        __syncthreads();          // visibility + all warps done with slot to be overwritten

        const float* As = Asm + cur*A_ELEMS;
        const float* Bs = Bsm + cur*B_ELEMS;
        #pragma unroll
        for (int ks = 0; ks < 2; ks++) {
            int kb = ks*8;
            uint32_t af[4][4], bf[4][2];
            #pragma unroll
            for (int mt = 0; mt < 4; mt++) {
                int rm = mw + mt*16;
                af[mt][0] = __float_as_uint(As[(rm + g    )*ASTRIDE + kb + tig    ]);
                af[mt][1] = __float_as_uint(As[(rm + g + 8)*ASTRIDE + kb + tig    ]);
                af[mt][2] = __float_as_uint(As[(rm + g    )*ASTRIDE + kb + tig + 4]);
                af[mt][3] = __float_as_uint(As[(rm + g + 8)*ASTRIDE + kb + tig + 4]);
            }
            #pragma unroll
            for (int nt = 0; nt < 4; nt++) {
                int cn = nw + nt*8;
                bf[nt][0] = __float_as_uint(Bs[(kb + tig    )*BSTRIDE + cn + g]);
                bf[nt][1] = __float_as_uint(Bs[(kb + tig + 4)*BSTRIDE + cn + g]);
            }
            #pragma unroll
            for (int mt = 0; mt < 4; mt++)
                #pragma unroll
                for (int nt = 0; nt < 4; nt++)
                    MMA_TF32(acc[mt][nt], af[mt][0], af[mt][1], af[mt][2], af[mt][3],
                             bf[nt][0], bf[nt][1]);
        }

        // issue loads for stage it+STAGES-1 into the slot freed last iteration
        if (it + STAGES-1 < nIter) {
            int s = (it + STAGES-1) % STAGES;
            loadStage(it + STAGES-1, s);
        }
        CP_COMMIT();

        cur = (cur + 1 == STAGES) ? 0 : cur + 1;
    }

    #pragma unroll
    for (int mt = 0; mt < 4; mt++) {
        int row0 = bm + mw + mt*16 + g;
        #pragma unroll
        for (int nt = 0; nt < 4; nt++) {
            int col = bn + nw + nt*8 + tig*2;
            if (col < N) {
                float b0 = bias[col], b1 = bias[col+1];
                float v0 = acc[mt][nt][0] + b0;
                float v1 = acc[mt][nt][1] + b1;
                float v2 = acc[mt][nt][2] + b0;
                float v3 = acc[mt][nt][3] + b1;
                if (act == 1) { v0 = gelu_f(v0); v1 = gelu_f(v1); v2 = gelu_f(v2); v3 = gelu_f(v3); }
                *(float2*)&C[(size_t)row0*ldc + col]     = make_float2(v0, v1);
                *(float2*)&C[(size_t)(row0+8)*ldc + col] = make_float2(v2, v3);
            }
        }
    }
}

// ---------------- tensor-core attention v2 (unchanged from R9) ----------------
#define AQ_STRIDE 68
#define AP_STRIDE 212
#define AT_STRIDE 72
#define AQ_ELEMS (64*AQ_STRIDE)
#define AP_ELEMS (64*AP_STRIDE)
#define AT_ELEMS (64*AT_STRIDE)
#define ATTN_SMEM ((AQ_ELEMS + AP_ELEMS + AT_ELEMS + 64)*4 + 256)

__global__ __launch_bounds__(256, 2) void attn_kernel(
        const float* __restrict__ qkv,
        const unsigned char* __restrict__ mask,
        float* __restrict__ out) {
    extern __shared__ float sm[];
    float* Qs  = sm;
    float* Ps  = Qs + AQ_ELEMS;
    float* Tb  = Ps + AP_ELEMS;
    float* inv = Tb + AT_ELEMS;
    unsigned char* mk = (unsigned char*)(inv + 64);

    int bh = blockIdx.y;
    int b = bh / NHEAD, h = bh % NHEAD;
    int qbase = blockIdx.x * 64;
    int tid = threadIdx.x;
    int warp = tid >> 5, lane = tid & 31;
    int g = lane >> 2, tig = lane & 3;
    int wm = (warp >> 1)*16;
    int wn = warp & 1;

    const float* base = qkv + (size_t)b*SEQ*900;
    const float scale = 0.1414213562373095f;  // 1/sqrt(50)

    if (tid < SEQ) mk[tid] = mask[b*SEQ + tid];
    int padcnt = __syncthreads_count(tid < SEQ && mask[b*SEQ + tid]);
    bool allpad = (padcnt == SEQ);

    for (int i = tid; i < AQ_ELEMS; i += 256) {
        int r = i / AQ_STRIDE, d = i % AQ_STRIDE;
        int q = qbase + r;
        float v = (q < SEQ && d < DHEAD) ? base[(size_t)q*900 + h*DHEAD + d]*scale : 0.0f;
        Qs[i] = to_tf32(v);
    }
    __syncthreads();

    for (int kt = 0; kt < 4; kt++) {
        int K0 = kt*64;
        for (int i = tid; i < 4096; i += 256) {
            int k = i >> 6, d = i & 63;
            float v = (K0 + k < SEQ && d < DHEAD)
                    ? base[(size_t)(K0+k)*900 + 300 + h*DHEAD + d] : 0.0f;
            Tb[d*AT_STRIDE + k] = to_tf32(v);
        }
        __syncthreads();

        float sacc[4][4];
        #pragma unroll
        for (int nt = 0; nt < 4; nt++)
            #pragma unroll
            for (int r = 0; r < 4; r++) sacc[nt][r] = 0.0f;
        #pragma unroll
        for (int ks = 0; ks < 8; ks++) {
            int kb = ks*8;
            uint32_t a0 = __float_as_uint(Qs[(wm + g    )*AQ_STRIDE + kb + tig    ]);
            uint32_t a1 = __float_as_uint(Qs[(wm + g + 8)*AQ_STRIDE + kb + tig    ]);
            uint32_t a2 = __float_as_uint(Qs[(wm + g    )*AQ_STRIDE + kb + tig + 4]);
            uint32_t a3 = __float_as_uint(Qs[(wm + g + 8)*AQ_STRIDE + kb + tig + 4]);
            #pragma unroll
            for (int nt = 0; nt < 4; nt++) {
                int cn = wn*32 + nt*8;
                uint32_t b0 = __float_as_uint(Tb[(kb + tig    )*AT_STRIDE + cn + g]);
                uint32_t b1 = __float_as_uint(Tb[(kb + tig + 4)*AT_STRIDE + cn + g]);
                MMA_TF32(sacc[nt], a0, a1, a2, a3, b0, b1);
            }
        }
        #pragma unroll
        for (int nt = 0; nt < 4; nt++) {
            int col = K0 + wn*32 + nt*8 + tig*2;
            if (col < 208) {
                *(float2*)&Ps[(wm + g    )*AP_STRIDE + col] = make_float2(sacc[nt][0], sacc[nt][1]);
                *(float2*)&Ps[(wm + g + 8)*AP_STRIDE + col] = make_float2(sacc[nt][2], sacc[nt][3]);
            }
        }
        __syncthreads();
    }

    {
        int row = tid >> 2, j = tid & 3;
        float m = -INFINITY;
        for (int k = j; k < SEQ; k += 4)
            if (!mk[k]) m = fmaxf(m, Ps[row*AP_STRIDE + k]);
        m = fmaxf(m, __shfl_xor_sync(0xffffffffu, m, 1));
        m = fmaxf(m, __shfl_xor_sync(0xffffffffu, m, 2));
        float ssum = 0.0f;
        for (int k = j; k < 208; k += 4) {
            float p = 0.0f;
            if (k < SEQ && !mk[k]) {
                p = __expf(Ps[row*AP_STRIDE + k] - m);
                ssum += p;
            }
            Ps[row*AP_STRIDE + k] = to_tf32(p);
        }
        ssum += __shfl_xor_sync(0xffffffffu, ssum, 1);
        ssum += __shfl_xor_sync(0xffffffffu, ssum, 2);
        if (j == 0) inv[row] = (allpad || ssum == 0.0f) ? 0.0f : 1.0f/ssum;
    }
    __syncthreads();

    float oacc[4][4];
    #pragma unroll
    for (int nt = 0; nt < 4; nt++)
        #pragma unroll
        for (int r = 0; r < 4; r++) oacc[nt][r] = 0.0f;

    for (int kt = 0; kt < 4; kt++) {
        int K0 = kt*64;
        int nk = (kt == 3) ? 2 : 8;
        for (int i = tid; i < 4096; i += 256) {
            int k = i >> 6, d = i & 63;
            float v = (K0 + k < SEQ && d < DHEAD)
                    ? base[(size_t)(K0+k)*900 + 600 + h*DHEAD + d] : 0.0f;
            Tb[k*AT_STRIDE + d] = to_tf32(v);
        }
        __syncthreads();

        for (int ks = 0; ks < nk; ks++) {
            int kb = ks*8;
            uint32_t a0 = __float_as_uint(Ps[(wm + g    )*AP_STRIDE + K0 + kb + tig    ]);
            uint32_t a1 = __float_as_uint(Ps[(wm + g + 8)*AP_STRIDE + K0 + kb + tig    ]);
            uint32_t a2 = __float_as_uint(Ps[(wm + g    )*AP_STRIDE + K0 + kb + tig + 4]);
            uint32_t a3 = __float_as_uint(Ps[(wm + g + 8)*AP_STRIDE + K0 + kb + tig + 4]);
            #pragma unroll
            for (int nt = 0; nt < 4; nt++) {
                int cn = wn*32 + nt*8;
                uint32_t b0 = __float_as_uint(Tb[(kb + tig    )*AT_STRIDE + cn + g]);
                uint32_t b1 = __float_as_uint(Tb[(kb + tig + 4)*AT_STRIDE + cn + g]);
                MMA_TF32(oacc[nt], a0, a1, a2, a3, b0, b1);
            }
        }
        __syncthreads();
    }

    {
        float v0 = inv[wm + g], v1 = inv[wm + g + 8];
        int q0 = qbase + wm + g;
        #pragma unroll
        for (int nt = 0; nt < 4; nt++) {
            int col = wn*32 + nt*8 + tig*2;
            if (col < DHEAD) {
                if (q0 < SEQ)
                    *(float2*)&out[(size_t)(b*SEQ + q0)*LDH + h*DHEAD + col] =
                        make_float2(oacc[nt][0]*v0, oacc[nt][1]*v0);
                if (q0 + 8 < SEQ)
                    *(float2*)&out[(size_t)(b*SEQ + q0 + 8)*LDH + h*DHEAD + col] =
                        make_float2(oacc[nt][2]*v1, oacc[nt][3]*v1);
            }
        }
    }
}

// ---------------- warp-per-row residual add + LayerNorm -----------------------
__global__ void ln_kernel(const float* __restrict__ X,
                          const float* __restrict__ Y,
                          const float* __restrict__ s,
                          const float* __restrict__ bcoef,
                          float* __restrict__ out,
                          unsigned char* maskout) {
    int tid = threadIdx.x, warp = tid >> 5, lane = tid & 31;
    int r = blockIdx.x*8 + warp;      // 256 threads = 8 warps, 1 row each
    if (r >= NROW) return;

    float v[10]; int nd = 0;
    float sum = 0.0f;
    for (int d = lane; d < DIM; d += 32) {
        float t = X[(size_t)r*LDH + d] + Y[(size_t)r*LDH + d];
        v[nd++] = t;
        sum += t;
    }
    #pragma unroll
    for (int off = 16; off > 0; off >>= 1) sum += __shfl_xor_sync(0xffffffffu, sum, off);
    float mean = sum / (float)DIM;

    float var = 0.0f;
    for (int i = 0; i < nd; i++) { float d0 = v[i] - mean; var += d0*d0; }
    #pragma unroll
    for (int off = 16; off > 0; off >>= 1) var += __shfl_xor_sync(0xffffffffu, var, off);
    float rstd = 1.0f / sqrtf(var/(float)DIM + 1e-5f);

    bool allz = true;
    int i2 = 0;
    for (int d = lane; d < DIM; d += 32) {
        float o = (v[i2++] - mean)*rstd*s[d] + bcoef[d];
        out[(size_t)r*LDH + d] = o;
        if (o != 0.0f) allz = false;
    }
    if (maskout) {
        bool all = __all_sync(0xffffffffu, allz);
        if (lane == 0) maskout[r] = all ? 1 : 0;
    }
}

// ---------------- head kernels ------------------------------------------------
__global__ void rowdot_kernel(const float* __restrict__ w1,
                              const float* __restrict__ b1) {
    int tid = threadIdx.x, warp = tid >> 5, lane = tid & 31;
    int r = blockIdx.x*8 + warp;
    if (r >= NROW) return;
    float acc = 0.0f;
    for (int d = lane; d < DIM; d += 32)
        acc += g_h[(size_t)r*LDH + d] * w1[d];
    #pragma unroll
    for (int off = 16; off > 0; off >>= 1) acc += __shfl_xor_sync(0xffffffffu, acc, off);
    if (lane == 0) g_s1[r] = acc + b1[0];
}

__global__ void head_kernel(const float* __restrict__ w2, const float* __restrict__ b2,
                            const float* __restrict__ wo, const float* __restrict__ bo,
                            const float* __restrict__ wa, const float* __restrict__ ba,
                            float* __restrict__ out) {
    __shared__ float s1s[SEQ];
    __shared__ float s2s[50];
    int b = blockIdx.x, tid = threadIdx.x;     // 64 threads
    for (int i = tid; i < SEQ; i += 64) s1s[i] = g_s1[b*SEQ + i];
    __syncthreads();
    if (tid < 50) {
        float acc = 0.0f;
        for (int s = 0; s < SEQ; s++) acc += s1s[s]*w2[s*50 + tid];
        s2s[tid] = gelu_f(acc + b2[tid]);
    }
    __syncthreads();
    if (tid < 7) {
        float acc = 0.0f;
        if (tid == 0) {
            for (int i = 0; i < 50; i++) acc += s2s[i]*wo[i];
            out[b*7] = acc + bo[0];
        } else {
            int j = tid - 1;
            for (int i = 0; i < 50; i++) acc += s2s[i]*wa[i*6 + j];
            out[b*7 + tid] = acc + ba[j];
        }
    }
}

// ---------------- launch ------------------------------------------------------
extern "C" void kernel_launch(void* const* d_in, const int* in_sizes, int n_in,
                              void* d_out, int out_size) {
    const int*   x_tok  = (const int*)  d_in[0];
    const float* emb    = (const float*)d_in[1];
    const float* qkv_w  = (const float*)d_in[2];
    const float* qkv_b  = (const float*)d_in[3];
    const float* out_w  = (const float*)d_in[4];
    const float* out_b  = (const float*)d_in[5];
    const float* ln1_s  = (const float*)d_in[6];
    const float* ln1_b  = (const float*)d_in[7];
    const float* ff1_w  = (const float*)d_in[8];
    const float* ff1_b  = (const float*)d_in[9];
    const float* ff2_w  = (const float*)d_in[10];
    const float* ff2_b  = (const float*)d_in[11];
    const float* ln2_s  = (const float*)d_in[12];
    const float* ln2_b  = (const float*)d_in[13];
    const float* lin1_w = (const float*)d_in[14];
    const float* lin1_b = (const float*)d_in[15];
    const float* lin2_w = (const float*)d_in[16];
    const float* lin2_b = (const float*)d_in[17];
    const float* lout_w = (const float*)d_in[18];
    const float* lout_b = (const float*)d_in[19];
    const float* laux_w = (const float*)d_in[20];
    const float* laux_b = (const float*)d_in[21];

    float *p_h, *p_h1, *p_qkv, *p_att, *p_prj, *p_ff1, *p_ff2;
    float *p_wqkv, *p_wprj, *p_wff1, *p_wff2;
    unsigned char *p_mask;
    cudaGetSymbolAddress((void**)&p_h,   g_h);
    cudaGetSymbolAddress((void**)&p_h1,  g_h1);
    cudaGetSymbolAddress((void**)&p_qkv, g_qkv);
    cudaGetSymbolAddress((void**)&p_att, g_att);
    cudaGetSymbolAddress((void**)&p_prj, g_prj);
    cudaGetSymbolAddress((void**)&p_ff1, g_ff1);
    cudaGetSymbolAddress((void**)&p_ff2, g_ff2);
    cudaGetSymbolAddress((void**)&p_mask, g_mask);
    cudaGetSymbolAddress((void**)&p_wqkv, g_pw_qkv);
    cudaGetSymbolAddress((void**)&p_wprj, g_pw_prj);
    cudaGetSymbolAddress((void**)&p_wff1, g_pw_ff1);
    cudaGetSymbolAddress((void**)&p_wff2, g_pw_ff2);

    cudaFuncSetAttribute(attn_kernel, cudaFuncAttributeMaxDynamicSharedMemorySize,
                         ATTN_SMEM);
    cudaFuncSetAttribute(mma_gemm_kernel, cudaFuncAttributeMaxDynamicSharedMemorySize,
                         GEMM_SMEM);

    sin_table_kernel<<<(SEQ*DIM + 255)/256, 256>>>();
    embed_kernel<<<(NROW*DIM + 255)/256, 256>>>(x_tok, emb);
    pack_all_kernel<<<(PK_S1+PK_S2+PK_S3+PK_S4+255)/256, 256>>>(qkv_w, out_w, ff1_w, ff2_w);

    for (int l = 0; l < 5; l++) {
        mma_gemm_kernel<<<dim3(8, NROW/BM), 256, GEMM_SMEM>>>(p_h, p_wqkv + (size_t)l*320*1024,
            qkv_b + l*900, p_qkv, 900, 320, LDH, 1024, 900, 0);
        attn_kernel<<<dim3(4, BATCH*NHEAD), 256, ATTN_SMEM>>>(p_qkv, p_mask, p_att);
        mma_gemm_kernel<<<dim3(3, NROW/BM), 256, GEMM_SMEM>>>(p_att, p_wprj + (size_t)l*320*384,
            out_b + l*DIM, p_prj, 300, 320, LDH, 384, LDH, 0);
        ln_kernel<<<NROW/8, 256>>>(p_h, p_prj, ln1_s + l*DIM, ln1_b + l*DIM, p_h1, nullptr);
        mma_gemm_kernel<<<dim3(5, NROW/BM), 256, GEMM_SMEM>>>(p_h1, p_wff1 + (size_t)l*320*640,
            ff1_b + l*2*DIM, p_ff1, 600, 320, LDH, 640, LDF, 1);
        mma_gemm_kernel<<<dim3(3, NROW/BM), 256, GEMM_SMEM>>>(p_ff1, p_wff2 + (size_t)l*608*384,
            ff2_b + l*DIM, p_ff2, 300, 608, LDF, 384, LDH, 0);
        ln_kernel<<<NROW/8, 256>>>(p_h1, p_ff2, ln2_s + l*DIM, ln2_b + l*DIM, p_h, p_mask);
    }

    rowdot_kernel<<<NROW/8, 256>>>(lin1_w, lin1_b);
    head_kernel<<<BATCH, 64>>>(lin2_w, lin2_b, lout_w, lout_b, laux_w, laux_b,
                               (float*)d_out);
}

// round 11
// speedup vs baseline: 3.9033x; 1.2262x over previous
#include <cuda_runtime.h>
#include <cuda_bf16.h>
#include <math.h>
#include <stdint.h>

// Problem constants
#define BATCH 256
#define SEQ   200
#define DIM   300
#define NHEAD 6
#define DHEAD 50
#define NROW  (BATCH*SEQ)        // 51200
#define LDH   320                // padded stride for D=300 activations
#define LDF   608                // padded stride for 600-dim FF hidden
#define GELU_C 0.7978845608028654f

// ---------------- scratch (device globals; zero-initialized) ------------------
__device__ float g_sin[SEQ*DIM];
__device__ float g_h  [NROW*LDH];          // residual stream (fp32)
__device__ float g_h1 [NROW*LDH];          // post-LN1 (fp32)
__device__ float g_qkv[NROW*900];          // QKV activations (fp32, feeds attn)
__device__ float g_prj[NROW*LDH];          // proj output (fp32)
__device__ float g_ff2[NROW*LDH];          // ff2 output (fp32)
__device__ float g_s1 [NROW];
__device__ unsigned char g_mask[NROW];

// bf16 GEMM inputs (pads never written -> stay zero)
__device__ __nv_bfloat16 g_hb [NROW*LDH];  // bf16 copy of g_h
__device__ __nv_bfloat16 g_h1b[NROW*LDH];  // bf16 copy of g_h1
__device__ __nv_bfloat16 g_att[NROW*LDH];  // attention out (feeds prj gemm)
__device__ __nv_bfloat16 g_ff1[NROW*LDF];  // ff1 out (feeds ff2 gemm)

// packed bf16 weights: word w[kp][n] = {B[2kp][n], B[2kp+1][n]}, zero padded
#define QKV_W (160*1024)
#define PRJ_W (160*384)
#define FF1_W (160*640)
#define FF2_W (304*384)
__device__ uint32_t g_pw_qkv[5*QKV_W];
__device__ uint32_t g_pw_prj[5*PRJ_W];
__device__ uint32_t g_pw_ff1[5*FF1_W];
__device__ uint32_t g_pw_ff2[5*FF2_W];

__device__ __forceinline__ float gelu_f(float x) {
    float x3 = x*x*x;
    return 0.5f*x*(1.0f + tanhf(GELU_C*(x + 0.044715f*x3)));
}
__device__ __forceinline__ float to_tf32(float v) {
    uint32_t t;
    asm("cvt.rna.tf32.f32 %0, %1;" : "=r"(t) : "f"(v));
    return __uint_as_float(t);
}
__device__ __forceinline__ uint32_t smemu32(const void* p) {
    return (uint32_t)__cvta_generic_to_shared(p);
}
#define CP16(dst, src) asm volatile("cp.async.cg.shared.global [%0], [%1], 16;\n" :: "r"(dst), "l"(src))
#define CP_COMMIT()    asm volatile("cp.async.commit_group;\n" ::)
#define CP_WAIT(N)     asm volatile("cp.async.wait_group %0;\n" :: "n"(N))

#define MMA_TF32(acc, a0,a1,a2,a3, b0,b1) \
    asm volatile( \
        "mma.sync.aligned.m16n8k8.row.col.f32.tf32.tf32.f32 " \
        "{%0,%1,%2,%3}, {%4,%5,%6,%7}, {%8,%9}, {%0,%1,%2,%3};" \
        : "+f"((acc)[0]), "+f"((acc)[1]), "+f"((acc)[2]), "+f"((acc)[3]) \
        : "r"(a0), "r"(a1), "r"(a2), "r"(a3), "r"(b0), "r"(b1))

#define MMA_BF16(acc, a0,a1,a2,a3, b0,b1) \
    asm volatile( \
        "mma.sync.aligned.m16n8k16.row.col.f32.bf16.bf16.f32 " \
        "{%0,%1,%2,%3}, {%4,%5,%6,%7}, {%8,%9}, {%0,%1,%2,%3};" \
        : "+f"((acc)[0]), "+f"((acc)[1]), "+f"((acc)[2]), "+f"((acc)[3]) \
        : "r"(a0), "r"(a1), "r"(a2), "r"(a3), "r"(b0), "r"(b1))

// ---------------- sinusoid table ----------------------------------------------
__global__ void sin_table_kernel() {
    int idx = blockIdx.x*blockDim.x + threadIdx.x;
    if (idx >= SEQ*DIM) return;
    int pos = idx / DIM, i = idx % DIM;
    double ang = (double)pos / pow(10000.0, 2.0*(double)(i/2)/(double)DIM);
    g_sin[idx] = (float)((i & 1) ? cos(ang) : sin(ang));
}

// ---------------- embedding + pos-enc + initial mask --------------------------
__global__ void embed_kernel(const int* __restrict__ tok,
                             const float* __restrict__ emb) {
    int idx = blockIdx.x*blockDim.x + threadIdx.x;
    if (idx >= NROW*DIM) return;
    int r = idx / DIM, d = idx % DIM;
    int t = tok[r];
    float v = emb[(size_t)t*DIM + d];
    if (t != 0) v += g_sin[(r % SEQ)*DIM + d];
    g_h [(size_t)r*LDH + d] = v;
    g_hb[(size_t)r*LDH + d] = __float2bfloat16_rn(v);
    if (d == 0) g_mask[r] = (t == 0) ? 1 : 0;
}

// ---------------- weight packing: fp32 [L,K,N] -> bf16 k-pair words -----------
__device__ __forceinline__ void pack_bf(const float* __restrict__ src,
                                        uint32_t* __restrict__ dst, int i,
                                        int K, int N, int Kpw, int Np) {
    int per = Kpw*Np;
    int l = i / per, r = i % per;
    int kp = r / Np, n = r % Np;
    float f0 = (2*kp   < K && n < N) ? src[(size_t)l*K*N + (size_t)(2*kp  )*N + n] : 0.0f;
    float f1 = (2*kp+1 < K && n < N) ? src[(size_t)l*K*N + (size_t)(2*kp+1)*N + n] : 0.0f;
    __nv_bfloat162 p = __floats2bfloat162_rn(f0, f1);   // .x = f0 (low)
    dst[i] = *reinterpret_cast<uint32_t*>(&p);
}
__global__ void pack_all_kernel(const float* __restrict__ qkv_w,
                                const float* __restrict__ out_w,
                                const float* __restrict__ ff1_w,
                                const float* __restrict__ ff2_w) {
    int i = blockIdx.x*blockDim.x + threadIdx.x;
    if (i < 5*QKV_W) { pack_bf(qkv_w, g_pw_qkv, i, 300, 900, 160, 1024); return; }
    i -= 5*QKV_W;
    if (i < 5*PRJ_W) { pack_bf(out_w, g_pw_prj, i, 300, 300, 160, 384); return; }
    i -= 5*PRJ_W;
    if (i < 5*FF1_W) { pack_bf(ff1_w, g_pw_ff1, i, 300, 600, 160, 640); return; }
    i -= 5*FF1_W;
    if (i < 5*FF2_W) { pack_bf(ff2_w, g_pw_ff2, i, 600, 300, 304, 384); return; }
}

// ---------------- BF16 tensor-core GEMM (5-stage, single-sync) ----------------
// C[M,N] = A[M,Kp]@B[Kp,Np] + bias (+gelu). A bf16 (pads zero), B word-packed.
// BK = 32 elements = 16 words per stage.
#define BM 128
#define BN 128
#define STAGES 5
#define ASTRIDE 20        // words per A row (16 + 4 pad)
#define BSTRIDE 136       // words per B k-row (128 + 8 pad)
#define A_ELEMS (BM*ASTRIDE)
#define B_ELEMS (16*BSTRIDE)
#define GEMM_SMEM ((STAGES*(A_ELEMS + B_ELEMS))*4)   // 94720 bytes

__global__ __launch_bounds__(256, 2) void mma_gemm_kernel(
        const __nv_bfloat16* __restrict__ A, const uint32_t* __restrict__ Bw,
        const float* __restrict__ bias, void* __restrict__ Cv,
        int N, int Kp, int lda, int Np, int ldc, int act, int obf) {
    extern __shared__ uint32_t dsm[];
    uint32_t* Asm = dsm;
    uint32_t* Bsm = dsm + STAGES*A_ELEMS;

    int tid = threadIdx.x;
    int warp = tid >> 5, lane = tid & 31;
    int g = lane >> 2, tig = lane & 3;
    int mw = (warp >> 2)*64, nw = (warp & 3)*32;
    int bm = blockIdx.y*BM, bn = blockIdx.x*BN;

    const __nv_bfloat16* Abase = A + (size_t)bm*lda;
    const uint32_t* Bbase = Bw + bn;

    float acc[4][4][4];
    #pragma unroll
    for (int i = 0; i < 4; i++)
        #pragma unroll
        for (int j = 0; j < 4; j++)
            #pragma unroll
            for (int r = 0; r < 4; r++) acc[i][j][r] = 0.0f;

    int nIter = Kp / 32;

    // per-thread load coords
    int am0 = tid >> 2,          awc0 = (tid & 3)*4;          // word col {0,4,8,12}
    int am1 = (tid + 256) >> 2;
    int bk0 = tid >> 5,          bnc0 = (tid & 31)*4;         // n word col
    int bk1 = (tid + 256) >> 5;

    auto loadStage = [&](int it, int s) {
        int k0e = it*32;          // element k offset
        int k0w = it*16;          // word k offset
        uint32_t* As = Asm + s*A_ELEMS;
        uint32_t* Bs = Bsm + s*B_ELEMS;
        CP16(smemu32(&As[am0*ASTRIDE + awc0]), Abase + (size_t)am0*lda + k0e + awc0*2);
        CP16(smemu32(&As[am1*ASTRIDE + awc0]), Abase + (size_t)am1*lda + k0e + awc0*2);
        CP16(smemu32(&Bs[bk0*BSTRIDE + bnc0]), Bbase + (size_t)(k0w+bk0)*Np + bnc0);
        CP16(smemu32(&Bs[bk1*BSTRIDE + bnc0]), Bbase + (size_t)(k0w+bk1)*Np + bnc0);
    };

    #pragma unroll
    for (int s = 0; s < STAGES-1; s++) {
        loadStage(s, s);
        CP_COMMIT();
    }

    int cur = 0;
    for (int it = 0; it < nIter; it++) {
        CP_WAIT(STAGES-2);
        __syncthreads();

        const uint32_t* As = Asm + cur*A_ELEMS;
        const uint32_t* Bs = Bsm + cur*B_ELEMS;
        #pragma unroll
        for (int ks = 0; ks < 2; ks++) {
            int kb = ks*8;
            uint32_t af[4][4], bf[4][2];
            #pragma unroll
            for (int mt = 0; mt < 4; mt++) {
                int rm = mw + mt*16;
                af[mt][0] = As[(rm + g    )*ASTRIDE + kb + tig    ];
                af[mt][1] = As[(rm + g + 8)*ASTRIDE + kb + tig    ];
                af[mt][2] = As[(rm + g    )*ASTRIDE + kb + tig + 4];
                af[mt][3] = As[(rm + g + 8)*ASTRIDE + kb + tig + 4];
            }
            #pragma unroll
            for (int nt = 0; nt < 4; nt++) {
                int cn = nw + nt*8;
                bf[nt][0] = Bs[(kb + tig    )*BSTRIDE + cn + g];
                bf[nt][1] = Bs[(kb + tig + 4)*BSTRIDE + cn + g];
            }
            #pragma unroll
            for (int mt = 0; mt < 4; mt++)
                #pragma unroll
                for (int nt = 0; nt < 4; nt++)
                    MMA_BF16(acc[mt][nt], af[mt][0], af[mt][1], af[mt][2], af[mt][3],
                             bf[nt][0], bf[nt][1]);
        }

        if (it + STAGES-1 < nIter) {
            int s = (it + STAGES-1) % STAGES;
            loadStage(it + STAGES-1, s);
        }
        CP_COMMIT();
        cur = (cur + 1 == STAGES) ? 0 : cur + 1;
    }

    #pragma unroll
    for (int mt = 0; mt < 4; mt++) {
        int row0 = bm + mw + mt*16 + g;
        #pragma unroll
        for (int nt = 0; nt < 4; nt++) {
            int col = bn + nw + nt*8 + tig*2;
            if (col < N) {
                float b0 = bias[col], b1 = bias[col+1];
                float v0 = acc[mt][nt][0] + b0;
                float v1 = acc[mt][nt][1] + b1;
                float v2 = acc[mt][nt][2] + b0;
                float v3 = acc[mt][nt][3] + b1;
                if (act == 1) { v0 = gelu_f(v0); v1 = gelu_f(v1); v2 = gelu_f(v2); v3 = gelu_f(v3); }
                if (obf) {
                    __nv_bfloat16* C16 = (__nv_bfloat16*)Cv;
                    __nv_bfloat162 pa = __floats2bfloat162_rn(v0, v1);
                    __nv_bfloat162 pb = __floats2bfloat162_rn(v2, v3);
                    *(__nv_bfloat162*)&C16[(size_t)row0*ldc + col]     = pa;
                    *(__nv_bfloat162*)&C16[(size_t)(row0+8)*ldc + col] = pb;
                } else {
                    float* C = (float*)Cv;
                    *(float2*)&C[(size_t)row0*ldc + col]     = make_float2(v0, v1);
                    *(float2*)&C[(size_t)(row0+8)*ldc + col] = make_float2(v2, v3);
                }
            }
        }
    }
}

// ---------------- tensor-core attention (tf32, bf16 output) -------------------
#define AQ_STRIDE 68
#define AP_STRIDE 212
#define AT_STRIDE 72
#define AQ_ELEMS (64*AQ_STRIDE)
#define AP_ELEMS (64*AP_STRIDE)
#define AT_ELEMS (64*AT_STRIDE)
#define ATTN_SMEM ((AQ_ELEMS + AP_ELEMS + AT_ELEMS + 64)*4 + 256)

__global__ __launch_bounds__(256, 2) void attn_kernel(
        const float* __restrict__ qkv,
        const unsigned char* __restrict__ mask,
        __nv_bfloat16* __restrict__ out) {
    extern __shared__ float sm[];
    float* Qs  = sm;
    float* Ps  = Qs + AQ_ELEMS;
    float* Tb  = Ps + AP_ELEMS;
    float* inv = Tb + AT_ELEMS;
    unsigned char* mk = (unsigned char*)(inv + 64);

    int bh = blockIdx.y;
    int b = bh / NHEAD, h = bh % NHEAD;
    int qbase = blockIdx.x * 64;
    int tid = threadIdx.x;
    int warp = tid >> 5, lane = tid & 31;
    int g = lane >> 2, tig = lane & 3;
    int wm = (warp >> 1)*16;
    int wn = warp & 1;

    const float* base = qkv + (size_t)b*SEQ*900;
    const float scale = 0.1414213562373095f;  // 1/sqrt(50)

    if (tid < SEQ) mk[tid] = mask[b*SEQ + tid];
    int padcnt = __syncthreads_count(tid < SEQ && mask[b*SEQ + tid]);
    bool allpad = (padcnt == SEQ);

    for (int i = tid; i < AQ_ELEMS; i += 256) {
        int r = i / AQ_STRIDE, d = i % AQ_STRIDE;
        int q = qbase + r;
        float v = (q < SEQ && d < DHEAD) ? base[(size_t)q*900 + h*DHEAD + d]*scale : 0.0f;
        Qs[i] = to_tf32(v);
    }
    __syncthreads();

    for (int kt = 0; kt < 4; kt++) {
        int K0 = kt*64;
        for (int i = tid; i < 4096; i += 256) {
            int k = i >> 6, d = i & 63;
            float v = (K0 + k < SEQ && d < DHEAD)
                    ? base[(size_t)(K0+k)*900 + 300 + h*DHEAD + d] : 0.0f;
            Tb[d*AT_STRIDE + k] = to_tf32(v);
        }
        __syncthreads();

        float sacc[4][4];
        #pragma unroll
        for (int nt = 0; nt < 4; nt++)
            #pragma unroll
            for (int r = 0; r < 4; r++) sacc[nt][r] = 0.0f;
        #pragma unroll
        for (int ks = 0; ks < 8; ks++) {
            int kb = ks*8;
            uint32_t a0 = __float_as_uint(Qs[(wm + g    )*AQ_STRIDE + kb + tig    ]);
            uint32_t a1 = __float_as_uint(Qs[(wm + g + 8)*AQ_STRIDE + kb + tig    ]);
            uint32_t a2 = __float_as_uint(Qs[(wm + g    )*AQ_STRIDE + kb + tig + 4]);
            uint32_t a3 = __float_as_uint(Qs[(wm + g + 8)*AQ_STRIDE + kb + tig + 4]);
            #pragma unroll
            for (int nt = 0; nt < 4; nt++) {
                int cn = wn*32 + nt*8;
                uint32_t b0 = __float_as_uint(Tb[(kb + tig    )*AT_STRIDE + cn + g]);
                uint32_t b1 = __float_as_uint(Tb[(kb + tig + 4)*AT_STRIDE + cn + g]);
                MMA_TF32(sacc[nt], a0, a1, a2, a3, b0, b1);
            }
        }
        #pragma unroll
        for (int nt = 0; nt < 4; nt++) {
            int col = K0 + wn*32 + nt*8 + tig*2;
            if (col < 208) {
                *(float2*)&Ps[(wm + g    )*AP_STRIDE + col] = make_float2(sacc[nt][0], sacc[nt][1]);
                *(float2*)&Ps[(wm + g + 8)*AP_STRIDE + col] = make_float2(sacc[nt][2], sacc[nt][3]);
            }
        }
        __syncthreads();
    }

    {
        int row = tid >> 2, j = tid & 3;
        float m = -INFINITY;
        for (int k = j; k < SEQ; k += 4)
            if (!mk[k]) m = fmaxf(m, Ps[row*AP_STRIDE + k]);
        m = fmaxf(m, __shfl_xor_sync(0xffffffffu, m, 1));
        m = fmaxf(m, __shfl_xor_sync(0xffffffffu, m, 2));
        float ssum = 0.0f;
        for (int k = j; k < 208; k += 4) {
            float p = 0.0f;
            if (k < SEQ && !mk[k]) {
                p = __expf(Ps[row*AP_STRIDE + k] - m);
                ssum += p;
            }
            Ps[row*AP_STRIDE + k] = to_tf32(p);
        }
        ssum += __shfl_xor_sync(0xffffffffu, ssum, 1);
        ssum += __shfl_xor_sync(0xffffffffu, ssum, 2);
        if (j == 0) inv[row] = (allpad || ssum == 0.0f) ? 0.0f : 1.0f/ssum;
    }
    __syncthreads();

    float oacc[4][4];
    #pragma unroll
    for (int nt = 0; nt < 4; nt++)
        #pragma unroll
        for (int r = 0; r < 4; r++) oacc[nt][r] = 0.0f;

    for (int kt = 0; kt < 4; kt++) {
        int K0 = kt*64;
        int nk = (kt == 3) ? 2 : 8;
        for (int i = tid; i < 4096; i += 256) {
            int k = i >> 6, d = i & 63;
            float v = (K0 + k < SEQ && d < DHEAD)
                    ? base[(size_t)(K0+k)*900 + 600 + h*DHEAD + d] : 0.0f;
            Tb[k*AT_STRIDE + d] = to_tf32(v);
        }
        __syncthreads();

        for (int ks = 0; ks < nk; ks++) {
            int kb = ks*8;
            uint32_t a0 = __float_as_uint(Ps[(wm + g    )*AP_STRIDE + K0 + kb + tig    ]);
            uint32_t a1 = __float_as_uint(Ps[(wm + g + 8)*AP_STRIDE + K0 + kb + tig    ]);
            uint32_t a2 = __float_as_uint(Ps[(wm + g    )*AP_STRIDE + K0 + kb + tig + 4]);
            uint32_t a3 = __float_as_uint(Ps[(wm + g + 8)*AP_STRIDE + K0 + kb + tig + 4]);
            #pragma unroll
            for (int nt = 0; nt < 4; nt++) {
                int cn = wn*32 + nt*8;
                uint32_t b0 = __float_as_uint(Tb[(kb + tig    )*AT_STRIDE + cn + g]);
                uint32_t b1 = __float_as_uint(Tb[(kb + tig + 4)*AT_STRIDE + cn + g]);
                MMA_TF32(oacc[nt], a0, a1, a2, a3, b0, b1);
            }
        }
        __syncthreads();
    }

    {
        float v0 = inv[wm + g], v1 = inv[wm + g + 8];
        int q0 = qbase + wm + g;
        #pragma unroll
        for (int nt = 0; nt < 4; nt++) {
            int col = wn*32 + nt*8 + tig*2;
            if (col < DHEAD) {
                if (q0 < SEQ) {
                    __nv_bfloat162 p = __floats2bfloat162_rn(oacc[nt][0]*v0, oacc[nt][1]*v0);
                    *(__nv_bfloat162*)&out[(size_t)(b*SEQ + q0)*LDH + h*DHEAD + col] = p;
                }
                if (q0 + 8 < SEQ) {
                    __nv_bfloat162 p = __floats2bfloat162_rn(oacc[nt][2]*v1, oacc[nt][3]*v1);
                    *(__nv_bfloat162*)&out[(size_t)(b*SEQ + q0 + 8)*LDH + h*DHEAD + col] = p;
                }
            }
        }
    }
}

// ---------------- warp-per-row residual add + LayerNorm -----------------------
__global__ void ln_kernel(const float* __restrict__ X,
                          const float* __restrict__ Y,
                          const float* __restrict__ s,
                          const float* __restrict__ bcoef,
                          float* __restrict__ out,
                          __nv_bfloat16* __restrict__ outb,
                          unsigned char* maskout) {
    int tid = threadIdx.x, warp = tid >> 5, lane = tid & 31;
    int r = blockIdx.x*8 + warp;
    if (r >= NROW) return;

    float v[10]; int nd = 0;
    float sum = 0.0f;
    for (int d = lane; d < DIM; d += 32) {
        float t = X[(size_t)r*LDH + d] + Y[(size_t)r*LDH + d];
        v[nd++] = t;
        sum += t;
    }
    #pragma unroll
    for (int off = 16; off > 0; off >>= 1) sum += __shfl_xor_sync(0xffffffffu, sum, off);
    float mean = sum / (float)DIM;

    float var = 0.0f;
    for (int i = 0; i < nd; i++) { float d0 = v[i] - mean; var += d0*d0; }
    #pragma unroll
    for (int off = 16; off > 0; off >>= 1) var += __shfl_xor_sync(0xffffffffu, var, off);
    float rstd = 1.0f / sqrtf(var/(float)DIM + 1e-5f);

    bool allz = true;
    int i2 = 0;
    for (int d = lane; d < DIM; d += 32) {
        float o = (v[i2++] - mean)*rstd*s[d] + bcoef[d];
        out[(size_t)r*LDH + d] = o;
        outb[(size_t)r*LDH + d] = __float2bfloat16_rn(o);
        if (o != 0.0f) allz = false;
    }
    if (maskout) {
        bool all = __all_sync(0xffffffffu, allz);
        if (lane == 0) maskout[r] = all ? 1 : 0;
    }
}

// ---------------- head kernels ------------------------------------------------
__global__ void rowdot_kernel(const float* __restrict__ w1,
                              const float* __restrict__ b1) {
    int tid = threadIdx.x, warp = tid >> 5, lane = tid & 31;
    int r = blockIdx.x*8 + warp;
    if (r >= NROW) return;
    float acc = 0.0f;
    for (int d = lane; d < DIM; d += 32)
        acc += g_h[(size_t)r*LDH + d] * w1[d];
    #pragma unroll
    for (int off = 16; off > 0; off >>= 1) acc += __shfl_xor_sync(0xffffffffu, acc, off);
    if (lane == 0) g_s1[r] = acc + b1[0];
}

__global__ void head_kernel(const float* __restrict__ w2, const float* __restrict__ b2,
                            const float* __restrict__ wo, const float* __restrict__ bo,
                            const float* __restrict__ wa, const float* __restrict__ ba,
                            float* __restrict__ out) {
    __shared__ float s1s[SEQ];
    __shared__ float s2s[50];
    int b = blockIdx.x, tid = threadIdx.x;     // 64 threads
    for (int i = tid; i < SEQ; i += 64) s1s[i] = g_s1[b*SEQ + i];
    __syncthreads();
    if (tid < 50) {
        float acc = 0.0f;
        for (int s = 0; s < SEQ; s++) acc += s1s[s]*w2[s*50 + tid];
        s2s[tid] = gelu_f(acc + b2[tid]);
    }
    __syncthreads();
    if (tid < 7) {
        float acc = 0.0f;
        if (tid == 0) {
            for (int i = 0; i < 50; i++) acc += s2s[i]*wo[i];
            out[b*7] = acc + bo[0];
        } else {
            int j = tid - 1;
            for (int i = 0; i < 50; i++) acc += s2s[i]*wa[i*6 + j];
            out[b*7 + tid] = acc + ba[j];
        }
    }
}

// ---------------- launch ------------------------------------------------------
extern "C" void kernel_launch(void* const* d_in, const int* in_sizes, int n_in,
                              void* d_out, int out_size) {
    const int*   x_tok  = (const int*)  d_in[0];
    const float* emb    = (const float*)d_in[1];
    const float* qkv_w  = (const float*)d_in[2];
    const float* qkv_b  = (const float*)d_in[3];
    const float* out_w  = (const float*)d_in[4];
    const float* out_b  = (const float*)d_in[5];
    const float* ln1_s  = (const float*)d_in[6];
    const float* ln1_b  = (const float*)d_in[7];
    const float* ff1_w  = (const float*)d_in[8];
    const float* ff1_b  = (const float*)d_in[9];
    const float* ff2_w  = (const float*)d_in[10];
    const float* ff2_b  = (const float*)d_in[11];
    const float* ln2_s  = (const float*)d_in[12];
    const float* ln2_b  = (const float*)d_in[13];
    const float* lin1_w = (const float*)d_in[14];
    const float* lin1_b = (const float*)d_in[15];
    const float* lin2_w = (const float*)d_in[16];
    const float* lin2_b = (const float*)d_in[17];
    const float* lout_w = (const float*)d_in[18];
    const float* lout_b = (const float*)d_in[19];
    const float* laux_w = (const float*)d_in[20];
    const float* laux_b = (const float*)d_in[21];

    float *p_h, *p_h1, *p_qkv, *p_prj, *p_ff2;
    __nv_bfloat16 *p_hb, *p_h1b, *p_att, *p_ff1;
    uint32_t *p_wqkv, *p_wprj, *p_wff1, *p_wff2;
    unsigned char *p_mask;
    cudaGetSymbolAddress((void**)&p_h,   g_h);
    cudaGetSymbolAddress((void**)&p_h1,  g_h1);
    cudaGetSymbolAddress((void**)&p_qkv, g_qkv);
    cudaGetSymbolAddress((void**)&p_prj, g_prj);
    cudaGetSymbolAddress((void**)&p_ff2, g_ff2);
    cudaGetSymbolAddress((void**)&p_hb,  g_hb);
    cudaGetSymbolAddress((void**)&p_h1b, g_h1b);
    cudaGetSymbolAddress((void**)&p_att, g_att);
    cudaGetSymbolAddress((void**)&p_ff1, g_ff1);
    cudaGetSymbolAddress((void**)&p_mask, g_mask);
    cudaGetSymbolAddress((void**)&p_wqkv, g_pw_qkv);
    cudaGetSymbolAddress((void**)&p_wprj, g_pw_prj);
    cudaGetSymbolAddress((void**)&p_wff1, g_pw_ff1);
    cudaGetSymbolAddress((void**)&p_wff2, g_pw_ff2);

    cudaFuncSetAttribute(attn_kernel, cudaFuncAttributeMaxDynamicSharedMemorySize,
                         ATTN_SMEM);
    cudaFuncSetAttribute(mma_gemm_kernel, cudaFuncAttributeMaxDynamicSharedMemorySize,
                         GEMM_SMEM);

    sin_table_kernel<<<(SEQ*DIM + 255)/256, 256>>>();
    embed_kernel<<<(NROW*DIM + 255)/256, 256>>>(x_tok, emb);
    {
        int total = 5*(QKV_W + PRJ_W + FF1_W + FF2_W);
        pack_all_kernel<<<(total + 255)/256, 256>>>(qkv_w, out_w, ff1_w, ff2_w);
    }

    for (int l = 0; l < 5; l++) {
        // QKV: [51200,320]bf16 @ [320,1024] -> fp32 [.,900]
        mma_gemm_kernel<<<dim3(8, NROW/BM), 256, GEMM_SMEM>>>(p_hb,
            p_wqkv + (size_t)l*QKV_W, qkv_b + l*900, p_qkv,
            900, 320, LDH, 1024, 900, 0, 0);
        attn_kernel<<<dim3(4, BATCH*NHEAD), 256, ATTN_SMEM>>>(p_qkv, p_mask, p_att);
        // proj: bf16 att @ [320,384] -> fp32
        mma_gemm_kernel<<<dim3(3, NROW/BM), 256, GEMM_SMEM>>>(p_att,
            p_wprj + (size_t)l*PRJ_W, out_b + l*DIM, p_prj,
            300, 320, LDH, 384, LDH, 0, 0);
        ln_kernel<<<NROW/8, 256>>>(p_h, p_prj, ln1_s + l*DIM, ln1_b + l*DIM,
                                   p_h1, p_h1b, nullptr);
        // FF1 + gelu: -> bf16 [.,608]
        mma_gemm_kernel<<<dim3(5, NROW/BM), 256, GEMM_SMEM>>>(p_h1b,
            p_wff1 + (size_t)l*FF1_W, ff1_b + l*2*DIM, p_ff1,
            600, 320, LDH, 640, LDF, 1, 1);
        // FF2: bf16 [.,608] @ [608,384] -> fp32
        mma_gemm_kernel<<<dim3(3, NROW/BM), 256, GEMM_SMEM>>>(p_ff1,
            p_wff2 + (size_t)l*FF2_W, ff2_b + l*DIM, p_ff2,
            300, 608, LDF, 384, LDH, 0, 0);
        ln_kernel<<<NROW/8, 256>>>(p_h1, p_ff2, ln2_s + l*DIM, ln2_b + l*DIM,
                                   p_h, p_hb, p_mask);
    }

    rowdot_kernel<<<NROW/8, 256>>>(lin1_w, lin1_b);
    head_kernel<<<BATCH, 64>>>(lin2_w, lin2_b, lout_w, lout_b, laux_w, laux_b,
                               (float*)d_out);
}